// round 3
// baseline (speedup 1.0000x reference)
#include <cuda_runtime.h>
#include <cuda_bf16.h>
#include <cstdint>

// Problem constants
#define B_WIN   4096      // windows*batch
#define NTOK    64        // tokens per window
#define CDIM    256
#define HEADS   8
#define HDIM    32
#define NW      64        // windows per image (mask count)
#define MROWS   (B_WIN * NTOK)          // 262144
#define QSCALE  0.17677669529663687f    // 32^-0.5

// Static scratch (allocation-free by rule)
__device__ float g_q[(size_t)B_WIN * HEADS * NTOK * HDIM];   // 256 MB
__device__ float g_k[(size_t)B_WIN * HEADS * NTOK * HDIM];   // 256 MB
__device__ float g_v[(size_t)B_WIN * HEADS * NTOK * HDIM];   // 256 MB
__device__ float g_ao[(size_t)MROWS * CDIM];                 // 256 MB

// ---------------------------------------------------------------------------
// NT SGEMM: C[M,N] = A[M,K] @ B[N,K]^T (+bias). 128x128x16 tiles, 8x8/thread.
// MODE 0: QKV epilogue -> scatter into g_q/g_k/g_v with bias + q scale.
// MODE 1: plain epilogue -> C[m*Ncols+o] = acc + bias[o]
// ---------------------------------------------------------------------------
template <int MODE>
__global__ __launch_bounds__(256)
void gemm_nt(const float* __restrict__ A, const float* __restrict__ B,
             const float* __restrict__ bias, float* __restrict__ C,
             int K, int Ncols)
{
    constexpr int BM = 128, BN = 128, BK = 16;
    __shared__ float As[BK][BM];
    __shared__ float Bs[BK][BN];

    const int tid = threadIdx.x;
    const int tx = tid & 15;          // 0..15 (N dir)
    const int ty = tid >> 4;          // 0..15 (M dir)

    const size_t mBase = (size_t)blockIdx.y * BM;
    const size_t nBase = (size_t)blockIdx.x * BN;

    const float* Ab = A + mBase * K;
    const float* Bb = B + nBase * K;

    float acc[8][8];
#pragma unroll
    for (int i = 0; i < 8; i++)
#pragma unroll
        for (int j = 0; j < 8; j++) acc[i][j] = 0.f;

    for (int k0 = 0; k0 < K; k0 += BK) {
#pragma unroll
        for (int r = 0; r < 2; r++) {
            int s   = tid + r * 256;      // 0..511
            int row = s >> 2;             // 0..127
            int kc  = (s & 3) * 4;        // 0,4,8,12
            float4 av = *(const float4*)(Ab + (size_t)row * K + k0 + kc);
            As[kc + 0][row] = av.x; As[kc + 1][row] = av.y;
            As[kc + 2][row] = av.z; As[kc + 3][row] = av.w;
            float4 bv = *(const float4*)(Bb + (size_t)row * K + k0 + kc);
            Bs[kc + 0][row] = bv.x; Bs[kc + 1][row] = bv.y;
            Bs[kc + 2][row] = bv.z; Bs[kc + 3][row] = bv.w;
        }
        __syncthreads();

#pragma unroll
        for (int k = 0; k < BK; k++) {
            float4 a0 = *(const float4*)&As[k][ty * 8];
            float4 a1 = *(const float4*)&As[k][ty * 8 + 4];
            float4 b0 = *(const float4*)&Bs[k][tx * 8];
            float4 b1 = *(const float4*)&Bs[k][tx * 8 + 4];
            float af[8] = {a0.x, a0.y, a0.z, a0.w, a1.x, a1.y, a1.z, a1.w};
            float bf[8] = {b0.x, b0.y, b0.z, b0.w, b1.x, b1.y, b1.z, b1.w};
#pragma unroll
            for (int i = 0; i < 8; i++)
#pragma unroll
                for (int j = 0; j < 8; j++)
                    acc[i][j] = fmaf(af[i], bf[j], acc[i][j]);
        }
        __syncthreads();
    }

    const int m0 = (int)mBase + ty * 8;
    const int o0 = (int)nBase + tx * 8;

    if (MODE == 0) {
        // scatter into q/k/v [B, H, N, hd]
#pragma unroll
        for (int i = 0; i < 8; i++) {
            int m = m0 + i;
            int b = m >> 6;        // window index
            int n = m & 63;        // token
#pragma unroll
            for (int j = 0; j < 8; j++) {
                int o  = o0 + j;
                int c3 = o >> 8;           // 0=q 1=k 2=v
                int h  = (o >> 5) & 7;
                int d  = o & 31;
                float v = acc[i][j] + bias[o];
                size_t idx = ((((size_t)b * HEADS + h) * NTOK + n) * HDIM) + d;
                if (c3 == 0)      g_q[idx] = v * QSCALE;
                else if (c3 == 1) g_k[idx] = v;
                else              g_v[idx] = v;
            }
        }
    } else {
#pragma unroll
        for (int i = 0; i < 8; i++) {
            size_t m = (size_t)(m0 + i);
#pragma unroll
            for (int j = 0; j < 8; j++) {
                int o = o0 + j;
                C[m * Ncols + o] = acc[i][j] + bias[o];
            }
        }
    }
}

// ---------------------------------------------------------------------------
// Attention: one block per (window b, head h). 64 threads = 1 query row each.
// scores = q·k^T + bias(rel) + mask(window), softmax, @v -> g_ao[B,N,H,hd]
// ---------------------------------------------------------------------------
__global__ __launch_bounds__(64)
void attn_kernel(const float* __restrict__ mask,
                 const float* __restrict__ table,
                 const int* __restrict__ rel_index)
{
    const int bh = blockIdx.x;       // b*8 + h
    const int b  = bh >> 3;
    const int h  = bh & 7;
    const int t  = threadIdx.x;      // query row 0..63

    __shared__ float ks[NTOK * HDIM];   // 8 KB
    __shared__ float vs[NTOK * HDIM];   // 8 KB

    const float4* kb = (const float4*)(g_k + (size_t)bh * NTOK * HDIM);
    const float4* vb = (const float4*)(g_v + (size_t)bh * NTOK * HDIM);
#pragma unroll
    for (int r = 0; r < 8; r++) {
        int idx = r * 64 + t;           // coalesced over 512 float4
        ((float4*)ks)[idx] = kb[idx];
        ((float4*)vs)[idx] = vb[idx];
    }

    // q row into registers
    float q[32];
    {
        const float4* qrow = (const float4*)(g_q + (size_t)bh * NTOK * HDIM + (size_t)t * HDIM);
#pragma unroll
        for (int r = 0; r < 8; r++) {
            float4 v = qrow[r];
            q[r * 4 + 0] = v.x; q[r * 4 + 1] = v.y; q[r * 4 + 2] = v.z; q[r * 4 + 3] = v.w;
        }
    }
    __syncthreads();

    const int*   ri = rel_index + t * 64;
    const float* mr = mask + (size_t)(b & (NW - 1)) * (NTOK * NTOK) + t * 64;

    float sc[64];
    float mx = -1e30f;
#pragma unroll 4
    for (int j = 0; j < 64; j++) {
        const float4* kj = (const float4*)(ks + j * HDIM);
        float s = 0.f;
#pragma unroll
        for (int r = 0; r < 8; r++) {
            float4 kv = kj[r];
            s = fmaf(q[r * 4 + 0], kv.x, s);
            s = fmaf(q[r * 4 + 1], kv.y, s);
            s = fmaf(q[r * 4 + 2], kv.z, s);
            s = fmaf(q[r * 4 + 3], kv.w, s);
        }
        s += table[ri[j] * HEADS + h] + mr[j];
        sc[j] = s;
        mx = fmaxf(mx, s);
    }

    float sum = 0.f;
#pragma unroll
    for (int j = 0; j < 64; j++) {
        float e = __expf(sc[j] - mx);
        sc[j] = e;
        sum += e;
    }
    const float inv = 1.f / sum;

    float o[32];
#pragma unroll
    for (int d = 0; d < 32; d++) o[d] = 0.f;
#pragma unroll 4
    for (int j = 0; j < 64; j++) {
        float p = sc[j] * inv;
        const float4* vj = (const float4*)(vs + j * HDIM);
#pragma unroll
        for (int r = 0; r < 8; r++) {
            float4 vv = vj[r];
            o[r * 4 + 0] = fmaf(p, vv.x, o[r * 4 + 0]);
            o[r * 4 + 1] = fmaf(p, vv.y, o[r * 4 + 1]);
            o[r * 4 + 2] = fmaf(p, vv.z, o[r * 4 + 2]);
            o[r * 4 + 3] = fmaf(p, vv.w, o[r * 4 + 3]);
        }
    }

    // write to [B, N, H, hd] layout (= [M, C])
    float4* dst = (float4*)(g_ao + ((size_t)(b * NTOK + t) * CDIM) + h * HDIM);
#pragma unroll
    for (int r = 0; r < 8; r++)
        dst[r] = make_float4(o[r * 4], o[r * 4 + 1], o[r * 4 + 2], o[r * 4 + 3]);
}

// ---------------------------------------------------------------------------
extern "C" void kernel_launch(void* const* d_in, const int* in_sizes, int n_in,
                              void* d_out, int out_size)
{
    const float* x      = (const float*)d_in[0];   // [4096,64,256]
    const float* mask   = (const float*)d_in[1];   // [64,64,64]
    const float* qkv_w  = (const float*)d_in[2];   // [768,256]
    const float* qkv_b  = (const float*)d_in[3];   // [768]
    const float* proj_w = (const float*)d_in[4];   // [256,256]
    const float* proj_b = (const float*)d_in[5];   // [256]
    const float* table  = (const float*)d_in[6];   // [225,8]
    const int*   relidx = (const int*)d_in[7];     // [64,64]
    float* out = (float*)d_out;

    float* g_ao_ptr = nullptr;
    cudaGetSymbolAddress((void**)&g_ao_ptr, g_ao);

    // 1) QKV projection: [262144,256] @ [768,256]^T
    {
        dim3 grid(768 / 128, MROWS / 128);   // (6, 2048)
        gemm_nt<0><<<grid, 256>>>(x, qkv_w, qkv_b, nullptr, CDIM, 768);
    }
    // 2) windowed attention
    attn_kernel<<<B_WIN * HEADS, 64>>>(mask, table, relidx);
    // 3) output projection: [262144,256] @ [256,256]^T
    {
        dim3 grid(256 / 128, MROWS / 128);   // (2, 2048)
        gemm_nt<1><<<grid, 256>>>(g_ao_ptr, proj_w, proj_b, out, CDIM, CDIM);
    }
}

// round 4
// speedup vs baseline: 1.7416x; 1.7416x over previous
#include <cuda_runtime.h>
#include <cuda_bf16.h>
#include <cstdint>

// Problem constants
#define B_WIN   4096
#define NTOK    64
#define CDIM    256
#define HEADS   8
#define HDIM    32
#define NW      64
#define MROWS   (B_WIN * NTOK)          // 262144
#define QSCALE  0.17677669529663687f    // 32^-0.5

// Static scratch (allocation-free by rule)
__device__ float g_q[(size_t)B_WIN * HEADS * NTOK * HDIM];
__device__ float g_k[(size_t)B_WIN * HEADS * NTOK * HDIM];
__device__ float g_v[(size_t)B_WIN * HEADS * NTOK * HDIM];
__device__ float g_ao[(size_t)MROWS * CDIM];

__device__ __forceinline__ uint32_t f2tf32(float f) {
    uint32_t u;
    asm("cvt.rna.tf32.f32 %0, %1;" : "=r"(u) : "f"(f));
    return u;
}

__device__ __forceinline__ void mma_tf32(float* c, const uint32_t* a, const uint32_t* b) {
    asm volatile(
        "mma.sync.aligned.m16n8k8.row.col.f32.tf32.tf32.f32 "
        "{%0,%1,%2,%3}, {%4,%5,%6,%7}, {%8,%9}, {%0,%1,%2,%3};"
        : "+f"(c[0]), "+f"(c[1]), "+f"(c[2]), "+f"(c[3])
        : "r"(a[0]), "r"(a[1]), "r"(a[2]), "r"(a[3]), "r"(b[0]), "r"(b[1]));
}

// ---------------------------------------------------------------------------
// TF32 tensor-core NT GEMM: C[M,N] = A[M,K] @ B[N,K]^T (+bias)
// 128x128x32 block tile, 256 threads = 8 warps, warp tile 64x32.
// MODE 0: QKV epilogue -> scatter into g_q/g_k/g_v with bias + q scale.
// MODE 1: plain epilogue -> C[m*Ncols+o] = acc + bias[o]
// ---------------------------------------------------------------------------
template <int MODE>
__global__ __launch_bounds__(256, 2)
void gemm_tf32(const float* __restrict__ A, const float* __restrict__ B,
               const float* __restrict__ bias, float* __restrict__ C,
               int K, int Ncols)
{
    constexpr int BM = 128, BN = 128, BK = 32;
    constexpr int SR = 36;                    // padded row stride (floats): conflict-free frags
    __shared__ uint32_t As[BM * SR];          // [m][k], tf32
    __shared__ uint32_t Bs[BN * SR];          // [n][k], tf32

    const int tid  = threadIdx.x;
    const int lane = tid & 31;
    const int gid  = lane >> 2;               // 0..7
    const int tig  = lane & 3;                // 0..3
    const int warpId = tid >> 5;              // 0..7
    const int wm = (warpId & 1) * 64;         // warp M offset (2 warps in M)
    const int wn = (warpId >> 1) * 32;        // warp N offset (4 warps in N)

    const size_t mBase = (size_t)blockIdx.y * BM;
    const size_t nBase = (size_t)blockIdx.x * BN;
    const float* Ab = A + mBase * K;
    const float* Bb = B + nBase * K;

    float acc[4][4][4];
#pragma unroll
    for (int i = 0; i < 4; i++)
#pragma unroll
        for (int j = 0; j < 4; j++)
#pragma unroll
            for (int r = 0; r < 4; r++) acc[i][j][r] = 0.f;

    for (int k0 = 0; k0 < K; k0 += BK) {
        // ---- global -> smem (convert to tf32) ----
#pragma unroll
        for (int p = 0; p < 4; p++) {
            int idx = tid + p * 256;          // 0..1023
            int row = idx >> 3;               // 0..127
            int cv  = (idx & 7) * 4;          // 0,4,...,28
            float4 av = *(const float4*)(Ab + (size_t)row * K + k0 + cv);
            As[row * SR + cv + 0] = f2tf32(av.x);
            As[row * SR + cv + 1] = f2tf32(av.y);
            As[row * SR + cv + 2] = f2tf32(av.z);
            As[row * SR + cv + 3] = f2tf32(av.w);
            float4 bv = *(const float4*)(Bb + (size_t)row * K + k0 + cv);
            Bs[row * SR + cv + 0] = f2tf32(bv.x);
            Bs[row * SR + cv + 1] = f2tf32(bv.y);
            Bs[row * SR + cv + 2] = f2tf32(bv.z);
            Bs[row * SR + cv + 3] = f2tf32(bv.w);
        }
        __syncthreads();

        // ---- compute 4 k-steps of 8 ----
#pragma unroll
        for (int ks = 0; ks < 4; ks++) {
            const int kk = ks * 8;
            uint32_t a[4][4], b[4][2];
#pragma unroll
            for (int i = 0; i < 4; i++) {
                int base = (wm + 16 * i + gid) * SR + kk + tig;
                a[i][0] = As[base];
                a[i][1] = As[base + 8 * SR];
                a[i][2] = As[base + 4];
                a[i][3] = As[base + 8 * SR + 4];
            }
#pragma unroll
            for (int j = 0; j < 4; j++) {
                int base = (wn + 8 * j + gid) * SR + kk + tig;
                b[j][0] = Bs[base];
                b[j][1] = Bs[base + 4];
            }
#pragma unroll
            for (int i = 0; i < 4; i++)
#pragma unroll
                for (int j = 0; j < 4; j++)
                    mma_tf32(acc[i][j], a[i], b[j]);
        }
        __syncthreads();
    }

    // ---- epilogue ----
#pragma unroll
    for (int i = 0; i < 4; i++) {
#pragma unroll
        for (int j = 0; j < 4; j++) {
#pragma unroll
            for (int r = 0; r < 4; r++) {
                int m = (int)mBase + wm + 16 * i + gid + (r >> 1) * 8;
                int o = (int)nBase + wn + 8 * j + 2 * tig + (r & 1);
                float val = acc[i][j][r] + bias[o];
                if (MODE == 0) {
                    int b  = m >> 6;
                    int n  = m & 63;
                    int c3 = o >> 8;
                    int h  = (o >> 5) & 7;
                    int d  = o & 31;
                    size_t idx = ((((size_t)b * HEADS + h) * NTOK + n) * HDIM) + d;
                    if (c3 == 0)      g_q[idx] = val * QSCALE;
                    else if (c3 == 1) g_k[idx] = val;
                    else              g_v[idx] = val;
                } else {
                    C[(size_t)m * Ncols + o] = val;
                }
            }
        }
    }
}

// ---------------------------------------------------------------------------
// Attention: one block per (window b, head h). 64 threads = 1 query row each.
// ---------------------------------------------------------------------------
__global__ __launch_bounds__(64)
void attn_kernel(const float* __restrict__ mask,
                 const float* __restrict__ table,
                 const int* __restrict__ rel_index)
{
    const int bh = blockIdx.x;
    const int b  = bh >> 3;
    const int h  = bh & 7;
    const int t  = threadIdx.x;

    __shared__ float ks[NTOK * HDIM];
    __shared__ float vs[NTOK * HDIM];

    const float4* kb = (const float4*)(g_k + (size_t)bh * NTOK * HDIM);
    const float4* vb = (const float4*)(g_v + (size_t)bh * NTOK * HDIM);
#pragma unroll
    for (int r = 0; r < 8; r++) {
        int idx = r * 64 + t;
        ((float4*)ks)[idx] = kb[idx];
        ((float4*)vs)[idx] = vb[idx];
    }

    float q[32];
    {
        const float4* qrow = (const float4*)(g_q + (size_t)bh * NTOK * HDIM + (size_t)t * HDIM);
#pragma unroll
        for (int r = 0; r < 8; r++) {
            float4 v = qrow[r];
            q[r * 4 + 0] = v.x; q[r * 4 + 1] = v.y; q[r * 4 + 2] = v.z; q[r * 4 + 3] = v.w;
        }
    }
    __syncthreads();

    const int*   ri = rel_index + t * 64;
    const float* mr = mask + (size_t)(b & (NW - 1)) * (NTOK * NTOK) + t * 64;

    float sc[64];
    float mx = -1e30f;
#pragma unroll 4
    for (int j = 0; j < 64; j++) {
        const float4* kj = (const float4*)(ks + j * HDIM);
        float s = 0.f;
#pragma unroll
        for (int r = 0; r < 8; r++) {
            float4 kv = kj[r];
            s = fmaf(q[r * 4 + 0], kv.x, s);
            s = fmaf(q[r * 4 + 1], kv.y, s);
            s = fmaf(q[r * 4 + 2], kv.z, s);
            s = fmaf(q[r * 4 + 3], kv.w, s);
        }
        s += table[ri[j] * HEADS + h] + mr[j];
        sc[j] = s;
        mx = fmaxf(mx, s);
    }

    float sum = 0.f;
#pragma unroll
    for (int j = 0; j < 64; j++) {
        float e = __expf(sc[j] - mx);
        sc[j] = e;
        sum += e;
    }
    const float inv = 1.f / sum;

    float o[32];
#pragma unroll
    for (int d = 0; d < 32; d++) o[d] = 0.f;
#pragma unroll 4
    for (int j = 0; j < 64; j++) {
        float p = sc[j] * inv;
        const float4* vj = (const float4*)(vs + j * HDIM);
#pragma unroll
        for (int r = 0; r < 8; r++) {
            float4 vv = vj[r];
            o[r * 4 + 0] = fmaf(p, vv.x, o[r * 4 + 0]);
            o[r * 4 + 1] = fmaf(p, vv.y, o[r * 4 + 1]);
            o[r * 4 + 2] = fmaf(p, vv.z, o[r * 4 + 2]);
            o[r * 4 + 3] = fmaf(p, vv.w, o[r * 4 + 3]);
        }
    }

    float4* dst = (float4*)(g_ao + ((size_t)(b * NTOK + t) * CDIM) + h * HDIM);
#pragma unroll
    for (int r = 0; r < 8; r++)
        dst[r] = make_float4(o[r * 4], o[r * 4 + 1], o[r * 4 + 2], o[r * 4 + 3]);
}

// ---------------------------------------------------------------------------
extern "C" void kernel_launch(void* const* d_in, const int* in_sizes, int n_in,
                              void* d_out, int out_size)
{
    const float* x      = (const float*)d_in[0];
    const float* mask   = (const float*)d_in[1];
    const float* qkv_w  = (const float*)d_in[2];
    const float* qkv_b  = (const float*)d_in[3];
    const float* proj_w = (const float*)d_in[4];
    const float* proj_b = (const float*)d_in[5];
    const float* table  = (const float*)d_in[6];
    const int*   relidx = (const int*)d_in[7];
    float* out = (float*)d_out;

    float* g_ao_ptr = nullptr;
    cudaGetSymbolAddress((void**)&g_ao_ptr, g_ao);

    // 1) QKV projection: [262144,256] @ [768,256]^T (tf32 tensor cores)
    {
        dim3 grid(768 / 128, MROWS / 128);
        gemm_tf32<0><<<grid, 256>>>(x, qkv_w, qkv_b, nullptr, CDIM, 768);
    }
    // 2) windowed attention
    attn_kernel<<<B_WIN * HEADS, 64>>>(mask, table, relidx);
    // 3) output projection: [262144,256] @ [256,256]^T (tf32 tensor cores)
    {
        dim3 grid(256 / 128, MROWS / 128);
        gemm_tf32<1><<<grid, 256>>>(g_ao_ptr, proj_w, proj_b, out, CDIM, CDIM);
    }
}

// round 6
// speedup vs baseline: 1.7425x; 1.0005x over previous
#include <cuda_runtime.h>
#include <cuda_bf16.h>
#include <cstdint>

// Problem constants
#define B_WIN   4096
#define NTOK    64
#define CDIM    256
#define HEADS   8
#define HDIM    32
#define NW      64
#define MROWS   (B_WIN * NTOK)          // 262144
#define QSCALE  0.17677669529663687f    // 32^-0.5

// Static scratch (allocation-free by rule)
__device__ float g_q[(size_t)B_WIN * HEADS * NTOK * HDIM];
__device__ float g_k[(size_t)B_WIN * HEADS * NTOK * HDIM];
__device__ float g_v[(size_t)B_WIN * HEADS * NTOK * HDIM];
__device__ float g_ao[(size_t)MROWS * CDIM];
__device__ float g_biasH[HEADS * NTOK * NTOK];   // [h][q][k] pre-gathered rel bias

__device__ __forceinline__ uint32_t f2tf32(float f) {
    uint32_t u;
    asm("cvt.rna.tf32.f32 %0, %1;" : "=r"(u) : "f"(f));
    return u;
}

__device__ __forceinline__ void mma_tf32(float* c, const uint32_t* a, const uint32_t* b) {
    asm volatile(
        "mma.sync.aligned.m16n8k8.row.col.f32.tf32.tf32.f32 "
        "{%0,%1,%2,%3}, {%4,%5,%6,%7}, {%8,%9}, {%0,%1,%2,%3};"
        : "+f"(c[0]), "+f"(c[1]), "+f"(c[2]), "+f"(c[3])
        : "r"(a[0]), "r"(a[1]), "r"(a[2]), "r"(a[3]), "r"(b[0]), "r"(b[1]));
}

// ---------------------------------------------------------------------------
// Init: biasH[h][q][k] = table[rel_index[q*64+k] * 8 + h]
// ---------------------------------------------------------------------------
__global__ void bias_init_kernel(const float* __restrict__ table,
                                 const int* __restrict__ rel_index)
{
    int idx = blockIdx.x * blockDim.x + threadIdx.x;   // 0 .. 32767
    if (idx >= HEADS * NTOK * NTOK) return;
    int h  = idx >> 12;            // /4096
    int qk = idx & 4095;
    g_biasH[idx] = table[rel_index[qk] * HEADS + h];
}

// ---------------------------------------------------------------------------
// TF32 tensor-core NT GEMM: C[M,N] = A[M,K] @ B[N,K]^T (+bias)
// ---------------------------------------------------------------------------
template <int MODE>
__global__ __launch_bounds__(256, 2)
void gemm_tf32(const float* __restrict__ A, const float* __restrict__ B,
               const float* __restrict__ bias, float* __restrict__ C,
               int K, int Ncols)
{
    constexpr int BM = 128, BN = 128, BK = 32;
    constexpr int SR = 36;
    __shared__ uint32_t As[BM * SR];
    __shared__ uint32_t Bs[BN * SR];

    const int tid  = threadIdx.x;
    const int lane = tid & 31;
    const int gid  = lane >> 2;
    const int tig  = lane & 3;
    const int warpId = tid >> 5;
    const int wm = (warpId & 1) * 64;
    const int wn = (warpId >> 1) * 32;

    const size_t mBase = (size_t)blockIdx.y * BM;
    const size_t nBase = (size_t)blockIdx.x * BN;
    const float* Ab = A + mBase * K;
    const float* Bb = B + nBase * K;

    float acc[4][4][4];
#pragma unroll
    for (int i = 0; i < 4; i++)
#pragma unroll
        for (int j = 0; j < 4; j++)
#pragma unroll
            for (int r = 0; r < 4; r++) acc[i][j][r] = 0.f;

    for (int k0 = 0; k0 < K; k0 += BK) {
#pragma unroll
        for (int p = 0; p < 4; p++) {
            int idx = tid + p * 256;
            int row = idx >> 3;
            int cv  = (idx & 7) * 4;
            float4 av = *(const float4*)(Ab + (size_t)row * K + k0 + cv);
            As[row * SR + cv + 0] = f2tf32(av.x);
            As[row * SR + cv + 1] = f2tf32(av.y);
            As[row * SR + cv + 2] = f2tf32(av.z);
            As[row * SR + cv + 3] = f2tf32(av.w);
            float4 bv = *(const float4*)(Bb + (size_t)row * K + k0 + cv);
            Bs[row * SR + cv + 0] = f2tf32(bv.x);
            Bs[row * SR + cv + 1] = f2tf32(bv.y);
            Bs[row * SR + cv + 2] = f2tf32(bv.z);
            Bs[row * SR + cv + 3] = f2tf32(bv.w);
        }
        __syncthreads();

#pragma unroll
        for (int ks = 0; ks < 4; ks++) {
            const int kk = ks * 8;
            uint32_t a[4][4], b[4][2];
#pragma unroll
            for (int i = 0; i < 4; i++) {
                int base = (wm + 16 * i + gid) * SR + kk + tig;
                a[i][0] = As[base];
                a[i][1] = As[base + 8 * SR];
                a[i][2] = As[base + 4];
                a[i][3] = As[base + 8 * SR + 4];
            }
#pragma unroll
            for (int j = 0; j < 4; j++) {
                int base = (wn + 8 * j + gid) * SR + kk + tig;
                b[j][0] = Bs[base];
                b[j][1] = Bs[base + 4];
            }
#pragma unroll
            for (int i = 0; i < 4; i++)
#pragma unroll
                for (int j = 0; j < 4; j++)
                    mma_tf32(acc[i][j], a[i], b[j]);
        }
        __syncthreads();
    }

#pragma unroll
    for (int i = 0; i < 4; i++) {
#pragma unroll
        for (int j = 0; j < 4; j++) {
#pragma unroll
            for (int r = 0; r < 4; r++) {
                int m = (int)mBase + wm + 16 * i + gid + (r >> 1) * 8;
                int o = (int)nBase + wn + 8 * j + 2 * tig + (r & 1);
                float val = acc[i][j][r] + bias[o];
                if (MODE == 0) {
                    int b  = m >> 6;
                    int n  = m & 63;
                    int c3 = o >> 8;
                    int h  = (o >> 5) & 7;
                    int d  = o & 31;
                    size_t idx = ((((size_t)b * HEADS + h) * NTOK + n) * HDIM) + d;
                    if (c3 == 0)      g_q[idx] = val * QSCALE;
                    else if (c3 == 1) g_k[idx] = val;
                    else              g_v[idx] = val;
                } else {
                    C[(size_t)m * Ncols + o] = val;
                }
            }
        }
    }
}

// ---------------------------------------------------------------------------
// Attention v2: one block per (window, head), 64 threads = 1 query row each.
// mask+bias staged to smem with coalesced loads (the R4 bottleneck fix).
// ---------------------------------------------------------------------------
__global__ __launch_bounds__(64)
void attn_kernel(const float* __restrict__ mask)
{
    const int bh = blockIdx.x;
    const int b  = bh >> 3;
    const int h  = bh & 7;
    const int t  = threadIdx.x;

    __shared__ float ks[NTOK * HDIM];        // 8 KB
    __shared__ float vs[NTOK * HDIM];        // 8 KB
    __shared__ float sadd[NTOK * 65];        // 16.25 KB, padded rows

    const float4* kb = (const float4*)(g_k + (size_t)bh * NTOK * HDIM);
    const float4* vb = (const float4*)(g_v + (size_t)bh * NTOK * HDIM);
#pragma unroll
    for (int r = 0; r < 8; r++) {
        int idx = r * 64 + t;
        ((float4*)ks)[idx] = kb[idx];
        ((float4*)vs)[idx] = vb[idx];
    }

    // coalesced stage of mask+bias: row i, thread t -> column t
    {
        const float* mrow = mask    + (size_t)(b & (NW - 1)) * (NTOK * NTOK);
        const float* brow = g_biasH + (size_t)h * (NTOK * NTOK);
#pragma unroll 8
        for (int i = 0; i < NTOK; i++)
            sadd[i * 65 + t] = mrow[i * 64 + t] + brow[i * 64 + t];
    }

    float q[32];
    {
        const float4* qrow = (const float4*)(g_q + (size_t)bh * NTOK * HDIM + (size_t)t * HDIM);
#pragma unroll
        for (int r = 0; r < 8; r++) {
            float4 v = qrow[r];
            q[r * 4 + 0] = v.x; q[r * 4 + 1] = v.y; q[r * 4 + 2] = v.z; q[r * 4 + 3] = v.w;
        }
    }
    __syncthreads();

    const float* my = sadd + t * 65;

    float sc[64];
    float mx = -1e30f;
#pragma unroll 4
    for (int j = 0; j < 64; j++) {
        const float4* kj = (const float4*)(ks + j * HDIM);
        float s = my[j];
#pragma unroll
        for (int r = 0; r < 8; r++) {
            float4 kv = kj[r];
            s = fmaf(q[r * 4 + 0], kv.x, s);
            s = fmaf(q[r * 4 + 1], kv.y, s);
            s = fmaf(q[r * 4 + 2], kv.z, s);
            s = fmaf(q[r * 4 + 3], kv.w, s);
        }
        sc[j] = s;
        mx = fmaxf(mx, s);
    }

    float sum = 0.f;
#pragma unroll
    for (int j = 0; j < 64; j++) {
        float e = __expf(sc[j] - mx);
        sc[j] = e;
        sum += e;
    }
    const float inv = 1.f / sum;

    float o[32];
#pragma unroll
    for (int d = 0; d < 32; d++) o[d] = 0.f;
#pragma unroll 4
    for (int j = 0; j < 64; j++) {
        float p = sc[j] * inv;
        const float4* vj = (const float4*)(vs + j * HDIM);
#pragma unroll
        for (int r = 0; r < 8; r++) {
            float4 vv = vj[r];
            o[r * 4 + 0] = fmaf(p, vv.x, o[r * 4 + 0]);
            o[r * 4 + 1] = fmaf(p, vv.y, o[r * 4 + 1]);
            o[r * 4 + 2] = fmaf(p, vv.z, o[r * 4 + 2]);
            o[r * 4 + 3] = fmaf(p, vv.w, o[r * 4 + 3]);
        }
    }

    float4* dst = (float4*)(g_ao + ((size_t)(b * NTOK + t) * CDIM) + h * HDIM);
#pragma unroll
    for (int r = 0; r < 8; r++)
        dst[r] = make_float4(o[r * 4], o[r * 4 + 1], o[r * 4 + 2], o[r * 4 + 3]);
}

// ---------------------------------------------------------------------------
extern "C" void kernel_launch(void* const* d_in, const int* in_sizes, int n_in,
                              void* d_out, int out_size)
{
    const float* x      = (const float*)d_in[0];
    const float* mask   = (const float*)d_in[1];
    const float* qkv_w  = (const float*)d_in[2];
    const float* qkv_b  = (const float*)d_in[3];
    const float* proj_w = (const float*)d_in[4];
    const float* proj_b = (const float*)d_in[5];
    const float* table  = (const float*)d_in[6];
    const int*   relidx = (const int*)d_in[7];
    float* out = (float*)d_out;

    float* g_ao_ptr = nullptr;
    cudaGetSymbolAddress((void**)&g_ao_ptr, g_ao);

    // 0) pre-gather relative position bias per head
    bias_init_kernel<<<(HEADS * NTOK * NTOK + 255) / 256, 256>>>(table, relidx);

    // 1) QKV projection (tf32 tensor cores)
    {
        dim3 grid(768 / 128, MROWS / 128);
        gemm_tf32<0><<<grid, 256>>>(x, qkv_w, qkv_b, nullptr, CDIM, 768);
    }
    // 2) windowed attention
    attn_kernel<<<B_WIN * HEADS, 64>>>(mask);
    // 3) output projection (tf32 tensor cores)
    {
        dim3 grid(256 / 128, MROWS / 128);
        gemm_tf32<1><<<grid, 256>>>(g_ao_ptr, proj_w, proj_b, out, CDIM, CDIM);
    }
}

// round 7
// speedup vs baseline: 2.6594x; 1.5262x over previous
#include <cuda_runtime.h>
#include <cuda_bf16.h>
#include <cstdint>

// Problem constants
#define B_WIN   4096
#define NTOK    64
#define CDIM    256
#define HEADS   8
#define HDIM    32
#define NW      64
#define MROWS   (B_WIN * NTOK)          // 262144
#define QSCALE  0.17677669529663687f    // 32^-0.5

// Static scratch (allocation-free by rule)
__device__ float g_q[(size_t)B_WIN * HEADS * NTOK * HDIM];
__device__ float g_k[(size_t)B_WIN * HEADS * NTOK * HDIM];
__device__ float g_v[(size_t)B_WIN * HEADS * NTOK * HDIM];
__device__ float g_ao[(size_t)MROWS * CDIM];
__device__ float g_biasH[HEADS * NTOK * NTOK];   // [h][q][k] pre-gathered rel bias

__device__ __forceinline__ uint32_t f2tf32(float f) {
    uint32_t u;
    asm("cvt.rna.tf32.f32 %0, %1;" : "=r"(u) : "f"(f));
    return u;
}

__device__ __forceinline__ void mma_tf32(float* c, const uint32_t* a, const uint32_t* b) {
    asm volatile(
        "mma.sync.aligned.m16n8k8.row.col.f32.tf32.tf32.f32 "
        "{%0,%1,%2,%3}, {%4,%5,%6,%7}, {%8,%9}, {%0,%1,%2,%3};"
        : "+f"(c[0]), "+f"(c[1]), "+f"(c[2]), "+f"(c[3])
        : "r"(a[0]), "r"(a[1]), "r"(a[2]), "r"(a[3]), "r"(b[0]), "r"(b[1]));
}

// ---------------------------------------------------------------------------
// Init: biasH[h][q][k] = table[rel_index[q*64+k] * 8 + h]
// ---------------------------------------------------------------------------
__global__ void bias_init_kernel(const float* __restrict__ table,
                                 const int* __restrict__ rel_index)
{
    int idx = blockIdx.x * blockDim.x + threadIdx.x;
    if (idx >= HEADS * NTOK * NTOK) return;
    int h  = idx >> 12;
    int qk = idx & 4095;
    g_biasH[idx] = table[rel_index[qk] * HEADS + h];
}

// ---------------------------------------------------------------------------
// TF32 tensor-core NT GEMM: C[M,N] = A[M,K] @ B[N,K]^T (+bias)
// ---------------------------------------------------------------------------
template <int MODE>
__global__ __launch_bounds__(256, 2)
void gemm_tf32(const float* __restrict__ A, const float* __restrict__ B,
               const float* __restrict__ bias, float* __restrict__ C,
               int K, int Ncols)
{
    constexpr int BM = 128, BN = 128, BK = 32;
    constexpr int SR = 36;
    __shared__ uint32_t As[BM * SR];
    __shared__ uint32_t Bs[BN * SR];

    const int tid  = threadIdx.x;
    const int lane = tid & 31;
    const int gid  = lane >> 2;
    const int tig  = lane & 3;
    const int warpId = tid >> 5;
    const int wm = (warpId & 1) * 64;
    const int wn = (warpId >> 1) * 32;

    const size_t mBase = (size_t)blockIdx.y * BM;
    const size_t nBase = (size_t)blockIdx.x * BN;
    const float* Ab = A + mBase * K;
    const float* Bb = B + nBase * K;

    float acc[4][4][4];
#pragma unroll
    for (int i = 0; i < 4; i++)
#pragma unroll
        for (int j = 0; j < 4; j++)
#pragma unroll
            for (int r = 0; r < 4; r++) acc[i][j][r] = 0.f;

    for (int k0 = 0; k0 < K; k0 += BK) {
#pragma unroll
        for (int p = 0; p < 4; p++) {
            int idx = tid + p * 256;
            int row = idx >> 3;
            int cv  = (idx & 7) * 4;
            float4 av = *(const float4*)(Ab + (size_t)row * K + k0 + cv);
            As[row * SR + cv + 0] = f2tf32(av.x);
            As[row * SR + cv + 1] = f2tf32(av.y);
            As[row * SR + cv + 2] = f2tf32(av.z);
            As[row * SR + cv + 3] = f2tf32(av.w);
            float4 bv = *(const float4*)(Bb + (size_t)row * K + k0 + cv);
            Bs[row * SR + cv + 0] = f2tf32(bv.x);
            Bs[row * SR + cv + 1] = f2tf32(bv.y);
            Bs[row * SR + cv + 2] = f2tf32(bv.z);
            Bs[row * SR + cv + 3] = f2tf32(bv.w);
        }
        __syncthreads();

#pragma unroll
        for (int ks = 0; ks < 4; ks++) {
            const int kk = ks * 8;
            uint32_t a[4][4], b[4][2];
#pragma unroll
            for (int i = 0; i < 4; i++) {
                int base = (wm + 16 * i + gid) * SR + kk + tig;
                a[i][0] = As[base];
                a[i][1] = As[base + 8 * SR];
                a[i][2] = As[base + 4];
                a[i][3] = As[base + 8 * SR + 4];
            }
#pragma unroll
            for (int j = 0; j < 4; j++) {
                int base = (wn + 8 * j + gid) * SR + kk + tig;
                b[j][0] = Bs[base];
                b[j][1] = Bs[base + 4];
            }
#pragma unroll
            for (int i = 0; i < 4; i++)
#pragma unroll
                for (int j = 0; j < 4; j++)
                    mma_tf32(acc[i][j], a[i], b[j]);
        }
        __syncthreads();
    }

#pragma unroll
    for (int i = 0; i < 4; i++) {
#pragma unroll
        for (int j = 0; j < 4; j++) {
#pragma unroll
            for (int r = 0; r < 4; r++) {
                int m = (int)mBase + wm + 16 * i + gid + (r >> 1) * 8;
                int o = (int)nBase + wn + 8 * j + 2 * tig + (r & 1);
                float val = acc[i][j][r] + bias[o];
                if (MODE == 0) {
                    int b  = m >> 6;
                    int n  = m & 63;
                    int c3 = o >> 8;
                    int h  = (o >> 5) & 7;
                    int d  = o & 31;
                    size_t idx = ((((size_t)b * HEADS + h) * NTOK + n) * HDIM) + d;
                    if (c3 == 0)      g_q[idx] = val * QSCALE;
                    else if (c3 == 1) g_k[idx] = val;
                    else              g_v[idx] = val;
                } else {
                    C[(size_t)m * Ncols + o] = val;
                }
            }
        }
    }
}

// ---------------------------------------------------------------------------
// Attention v3: one block per (window, head), 64 threads = 1 query row each.
// ALL 64-iteration loops fully unrolled so sc[64] stays in registers
// (partial unroll forced it into local memory -> the R3..R6 1.7ms plateau).
// ---------------------------------------------------------------------------
__global__ __launch_bounds__(64)
void attn_kernel(const float* __restrict__ mask)
{
    const int bh = blockIdx.x;
    const int b  = bh >> 3;
    const int h  = bh & 7;
    const int t  = threadIdx.x;

    __shared__ float ks[NTOK * HDIM];        // 8 KB
    __shared__ float vs[NTOK * HDIM];        // 8 KB
    __shared__ float sadd[NTOK * 65];        // 16.25 KB, padded rows

    const float4* kb = (const float4*)(g_k + (size_t)bh * NTOK * HDIM);
    const float4* vb = (const float4*)(g_v + (size_t)bh * NTOK * HDIM);
#pragma unroll
    for (int r = 0; r < 8; r++) {
        int idx = r * 64 + t;
        ((float4*)ks)[idx] = kb[idx];
        ((float4*)vs)[idx] = vb[idx];
    }

    // coalesced stage of mask+bias: row i, thread t -> column t
    {
        const float* mrow = mask    + (size_t)(b & (NW - 1)) * (NTOK * NTOK);
        const float* brow = g_biasH + (size_t)h * (NTOK * NTOK);
#pragma unroll 8
        for (int i = 0; i < NTOK; i++)
            sadd[i * 65 + t] = mrow[i * 64 + t] + brow[i * 64 + t];
    }

    float q[32];
    {
        const float4* qrow = (const float4*)(g_q + (size_t)bh * NTOK * HDIM + (size_t)t * HDIM);
#pragma unroll
        for (int r = 0; r < 8; r++) {
            float4 v = qrow[r];
            q[r * 4 + 0] = v.x; q[r * 4 + 1] = v.y; q[r * 4 + 2] = v.z; q[r * 4 + 3] = v.w;
        }
    }
    __syncthreads();

    const float* my = sadd + t * 65;

    float sc[64];
    float mx = -1e30f;
#pragma unroll
    for (int j = 0; j < 64; j++) {
        const float4* kj = (const float4*)(ks + j * HDIM);
        float s = my[j];
#pragma unroll
        for (int r = 0; r < 8; r++) {
            float4 kv = kj[r];
            s = fmaf(q[r * 4 + 0], kv.x, s);
            s = fmaf(q[r * 4 + 1], kv.y, s);
            s = fmaf(q[r * 4 + 2], kv.z, s);
            s = fmaf(q[r * 4 + 3], kv.w, s);
        }
        sc[j] = s;
        mx = fmaxf(mx, s);
    }

    float sum = 0.f;
#pragma unroll
    for (int j = 0; j < 64; j++) {
        float e = __expf(sc[j] - mx);
        sc[j] = e;
        sum += e;
    }
    const float inv = 1.f / sum;

    float o[32];
#pragma unroll
    for (int d = 0; d < 32; d++) o[d] = 0.f;
#pragma unroll
    for (int j = 0; j < 64; j++) {
        float p = sc[j] * inv;
        const float4* vj = (const float4*)(vs + j * HDIM);
#pragma unroll
        for (int r = 0; r < 8; r++) {
            float4 vv = vj[r];
            o[r * 4 + 0] = fmaf(p, vv.x, o[r * 4 + 0]);
            o[r * 4 + 1] = fmaf(p, vv.y, o[r * 4 + 1]);
            o[r * 4 + 2] = fmaf(p, vv.z, o[r * 4 + 2]);
            o[r * 4 + 3] = fmaf(p, vv.w, o[r * 4 + 3]);
        }
    }

    float4* dst = (float4*)(g_ao + ((size_t)(b * NTOK + t) * CDIM) + h * HDIM);
#pragma unroll
    for (int r = 0; r < 8; r++)
        dst[r] = make_float4(o[r * 4], o[r * 4 + 1], o[r * 4 + 2], o[r * 4 + 3]);
}

// ---------------------------------------------------------------------------
extern "C" void kernel_launch(void* const* d_in, const int* in_sizes, int n_in,
                              void* d_out, int out_size)
{
    const float* x      = (const float*)d_in[0];
    const float* mask   = (const float*)d_in[1];
    const float* qkv_w  = (const float*)d_in[2];
    const float* qkv_b  = (const float*)d_in[3];
    const float* proj_w = (const float*)d_in[4];
    const float* proj_b = (const float*)d_in[5];
    const float* table  = (const float*)d_in[6];
    const int*   relidx = (const int*)d_in[7];
    float* out = (float*)d_out;

    float* g_ao_ptr = nullptr;
    cudaGetSymbolAddress((void**)&g_ao_ptr, g_ao);

    // 0) pre-gather relative position bias per head
    bias_init_kernel<<<(HEADS * NTOK * NTOK + 255) / 256, 256>>>(table, relidx);

    // 1) QKV projection (tf32 tensor cores)
    {
        dim3 grid(768 / 128, MROWS / 128);
        gemm_tf32<0><<<grid, 256>>>(x, qkv_w, qkv_b, nullptr, CDIM, 768);
    }
    // 2) windowed attention
    attn_kernel<<<B_WIN * HEADS, 64>>>(mask);
    // 3) output projection (tf32 tensor cores)
    {
        dim3 grid(256 / 128, MROWS / 128);
        gemm_tf32<1><<<grid, 256>>>(g_ao_ptr, proj_w, proj_b, out, CDIM, CDIM);
    }
}

// round 13
// speedup vs baseline: 2.7865x; 1.0478x over previous
#include <cuda_runtime.h>
#include <cuda_bf16.h>
#include <cstdint>

// Problem constants
#define B_WIN   4096
#define NTOK    64
#define CDIM    256
#define HEADS   8
#define HDIM    32
#define NW      64
#define MROWS   (B_WIN * NTOK)          // 262144
#define QSCALE  0.17677669529663687f    // 32^-0.5

// Static scratch (allocation-free by rule)
__device__ float g_q[(size_t)B_WIN * HEADS * NTOK * HDIM];
__device__ float g_k[(size_t)B_WIN * HEADS * NTOK * HDIM];
__device__ float g_v[(size_t)B_WIN * HEADS * NTOK * HDIM];
__device__ float g_ao[(size_t)MROWS * CDIM];
__device__ float g_biasH[HEADS * NTOK * NTOK];   // [h][q][k] pre-gathered rel bias

__device__ __forceinline__ uint32_t f2tf32(float f) {
    uint32_t u;
    asm("cvt.rna.tf32.f32 %0, %1;" : "=r"(u) : "f"(f));
    return u;
}
__device__ __forceinline__ uint32_t smem_u32(const void* p) {
    uint32_t a;
    asm("{ .reg .u64 t; cvta.to.shared.u64 t, %1; cvt.u32.u64 %0, t; }" : "=r"(a) : "l"(p));
    return a;
}
__device__ __forceinline__ void cp_async16(uint32_t dst, const void* src) {
    asm volatile("cp.async.cg.shared.global [%0], [%1], 16;" :: "r"(dst), "l"(src) : "memory");
}
#define CP_COMMIT() asm volatile("cp.async.commit_group;" ::: "memory")
#define CP_WAIT(n)  asm volatile("cp.async.wait_group %0;" :: "n"(n) : "memory")

__device__ __forceinline__ void mma_tf32(float* c, const uint32_t* a, const uint32_t* b) {
    asm volatile(
        "mma.sync.aligned.m16n8k8.row.col.f32.tf32.tf32.f32 "
        "{%0,%1,%2,%3}, {%4,%5,%6,%7}, {%8,%9}, {%0,%1,%2,%3};"
        : "+f"(c[0]), "+f"(c[1]), "+f"(c[2]), "+f"(c[3])
        : "r"(a[0]), "r"(a[1]), "r"(a[2]), "r"(a[3]), "r"(b[0]), "r"(b[1]));
}

// ---------------------------------------------------------------------------
// Init: biasH[h][q][k] = table[rel_index[q*64+k] * 8 + h]
// ---------------------------------------------------------------------------
__global__ void bias_init_kernel(const float* __restrict__ table,
                                 const int* __restrict__ rel_index)
{
    int idx = blockIdx.x * blockDim.x + threadIdx.x;
    if (idx >= HEADS * NTOK * NTOK) return;
    int h  = idx >> 12;
    int qk = idx & 4095;
    g_biasH[idx] = table[rel_index[qk] * HEADS + h];
}

// ---------------------------------------------------------------------------
// TF32 mma.sync GEMM with cp.async double-buffered pipeline.
// C[M,N] = A[M,256] @ B[N,256]^T (+bias). 128x128x32 tile, 256 thr, 8 warps.
// smem holds raw fp32 (cp.async), cvt->tf32 happens at fragment load.
// MODE 0: QKV scatter epilogue; MODE 1: plain epilogue.
// ---------------------------------------------------------------------------
#define GSR 36                      // padded row stride (floats); 144B rows, 16B-aligned
#define TILE_F (128 * GSR)          // floats per tile (4608)
#define STAGE_F (2 * TILE_F)        // A+B per stage (9216 floats)
#define GEMM_SMEM (2 * STAGE_F * 4) // bytes = 73728

template <int MODE>
__global__ __launch_bounds__(256, 2)
void gemm_tf32(const float* __restrict__ A, const float* __restrict__ B,
               const float* __restrict__ bias, float* __restrict__ C, int Ncols)
{
    extern __shared__ float sm[];   // [stage][A(4608) | B(4608)]
    const uint32_t smb = smem_u32(sm);

    const int tid  = threadIdx.x;
    const int lane = tid & 31;
    const int gid  = lane >> 2;
    const int tig  = lane & 3;
    const int warpId = tid >> 5;
    const int wm = (warpId & 1) * 64;
    const int wn = (warpId >> 1) * 32;

    const size_t mBase = (size_t)blockIdx.y * 128;
    const size_t nBase = (size_t)blockIdx.x * 128;
    const float* Ab = A + mBase * 256;
    const float* Bb = B + nBase * 256;

    // per-thread fixed part of the async-copy addressing
    const int crow = tid >> 3;          // base rows for chunks (c>>3 with c=tid+p*256)
    const int ccq  = tid & 7;           // 16B chunk within row

    // issue one stage's cp.async (A+B tiles, 32 k-cols at s*32)
    auto load_stage = [&](int s, int buf) {
        const float* As = Ab + s * 32;
        const float* Bs = Bb + s * 32;
        const uint32_t baseA = smb + (uint32_t)buf * STAGE_F * 4;
        const uint32_t baseB = baseA + TILE_F * 4;
#pragma unroll
        for (int p = 0; p < 4; p++) {
            int row = crow + p * 32;
            uint32_t off = (uint32_t)row * 144 + (uint32_t)ccq * 16;
            cp_async16(baseA + off, As + (size_t)row * 256 + ccq * 4);
            cp_async16(baseB + off, Bs + (size_t)row * 256 + ccq * 4);
        }
        CP_COMMIT();
    };

    float acc[4][4][4];
#pragma unroll
    for (int i = 0; i < 4; i++)
#pragma unroll
        for (int j = 0; j < 4; j++)
#pragma unroll
            for (int r = 0; r < 4; r++) acc[i][j][r] = 0.f;

    load_stage(0, 0);

    for (int s = 0; s < 8; s++) {
        const int buf = s & 1;
        if (s < 7) load_stage(s + 1, buf ^ 1);
        if (s < 7) { CP_WAIT(1); } else { CP_WAIT(0); }
        __syncthreads();

        const float* Asm = sm + buf * STAGE_F;
        const float* Bsm = Asm + TILE_F;

#pragma unroll
        for (int ks = 0; ks < 4; ks++) {
            const int kk = ks * 8;
            uint32_t a[4][4], b[4][2];
#pragma unroll
            for (int i = 0; i < 4; i++) {
                int base = (wm + 16 * i + gid) * GSR + kk + tig;
                a[i][0] = f2tf32(Asm[base]);
                a[i][1] = f2tf32(Asm[base + 8 * GSR]);
                a[i][2] = f2tf32(Asm[base + 4]);
                a[i][3] = f2tf32(Asm[base + 8 * GSR + 4]);
            }
#pragma unroll
            for (int j = 0; j < 4; j++) {
                int base = (wn + 8 * j + gid) * GSR + kk + tig;
                b[j][0] = f2tf32(Bsm[base]);
                b[j][1] = f2tf32(Bsm[base + 4]);
            }
#pragma unroll
            for (int i = 0; i < 4; i++)
#pragma unroll
                for (int j = 0; j < 4; j++)
                    mma_tf32(acc[i][j], a[i], b[j]);
        }
        __syncthreads();
    }

    // ---- epilogue ----
#pragma unroll
    for (int i = 0; i < 4; i++) {
#pragma unroll
        for (int j = 0; j < 4; j++) {
#pragma unroll
            for (int r = 0; r < 4; r++) {
                int m = (int)mBase + wm + 16 * i + gid + (r >> 1) * 8;
                int o = (int)nBase + wn + 8 * j + 2 * tig + (r & 1);
                float val = acc[i][j][r] + bias[o];
                if (MODE == 0) {
                    int b  = m >> 6;
                    int n  = m & 63;
                    int c3 = o >> 8;
                    int h  = (o >> 5) & 7;
                    int d  = o & 31;
                    size_t idx = ((((size_t)b * HEADS + h) * NTOK + n) * HDIM) + d;
                    if (c3 == 0)      g_q[idx] = val * QSCALE;
                    else if (c3 == 1) g_k[idx] = val;
                    else              g_v[idx] = val;
                } else {
                    C[(size_t)m * Ncols + o] = val;
                }
            }
        }
    }
}

// ---------------------------------------------------------------------------
// Attention: one block per (window, head), 64 threads = 1 query row each.
// (unchanged from R7 — fully unrolled, register-resident scores)
// ---------------------------------------------------------------------------
__global__ __launch_bounds__(64)
void attn_kernel(const float* __restrict__ mask)
{
    const int bh = blockIdx.x;
    const int b  = bh >> 3;
    const int h  = bh & 7;
    const int t  = threadIdx.x;

    __shared__ float ks[NTOK * HDIM];
    __shared__ float vs[NTOK * HDIM];
    __shared__ float sadd[NTOK * 65];

    const float4* kb = (const float4*)(g_k + (size_t)bh * NTOK * HDIM);
    const float4* vb = (const float4*)(g_v + (size_t)bh * NTOK * HDIM);
#pragma unroll
    for (int r = 0; r < 8; r++) {
        int idx = r * 64 + t;
        ((float4*)ks)[idx] = kb[idx];
        ((float4*)vs)[idx] = vb[idx];
    }

    {
        const float* mrow = mask    + (size_t)(b & (NW - 1)) * (NTOK * NTOK);
        const float* brow = g_biasH + (size_t)h * (NTOK * NTOK);
#pragma unroll 8
        for (int i = 0; i < NTOK; i++)
            sadd[i * 65 + t] = mrow[i * 64 + t] + brow[i * 64 + t];
    }

    float q[32];
    {
        const float4* qrow = (const float4*)(g_q + (size_t)bh * NTOK * HDIM + (size_t)t * HDIM);
#pragma unroll
        for (int r = 0; r < 8; r++) {
            float4 v = qrow[r];
            q[r * 4 + 0] = v.x; q[r * 4 + 1] = v.y; q[r * 4 + 2] = v.z; q[r * 4 + 3] = v.w;
        }
    }
    __syncthreads();

    const float* my = sadd + t * 65;

    float sc[64];
    float mx = -1e30f;
#pragma unroll
    for (int j = 0; j < 64; j++) {
        const float4* kj = (const float4*)(ks + j * HDIM);
        float s = my[j];
#pragma unroll
        for (int r = 0; r < 8; r++) {
            float4 kv = kj[r];
            s = fmaf(q[r * 4 + 0], kv.x, s);
            s = fmaf(q[r * 4 + 1], kv.y, s);
            s = fmaf(q[r * 4 + 2], kv.z, s);
            s = fmaf(q[r * 4 + 3], kv.w, s);
        }
        sc[j] = s;
        mx = fmaxf(mx, s);
    }

    float sum = 0.f;
#pragma unroll
    for (int j = 0; j < 64; j++) {
        float e = __expf(sc[j] - mx);
        sc[j] = e;
        sum += e;
    }
    const float inv = 1.f / sum;

    float o[32];
#pragma unroll
    for (int d = 0; d < 32; d++) o[d] = 0.f;
#pragma unroll
    for (int j = 0; j < 64; j++) {
        float p = sc[j] * inv;
        const float4* vj = (const float4*)(vs + j * HDIM);
#pragma unroll
        for (int r = 0; r < 8; r++) {
            float4 vv = vj[r];
            o[r * 4 + 0] = fmaf(p, vv.x, o[r * 4 + 0]);
            o[r * 4 + 1] = fmaf(p, vv.y, o[r * 4 + 1]);
            o[r * 4 + 2] = fmaf(p, vv.z, o[r * 4 + 2]);
            o[r * 4 + 3] = fmaf(p, vv.w, o[r * 4 + 3]);
        }
    }

    float4* dst = (float4*)(g_ao + ((size_t)(b * NTOK + t) * CDIM) + h * HDIM);
#pragma unroll
    for (int r = 0; r < 8; r++)
        dst[r] = make_float4(o[r * 4], o[r * 4 + 1], o[r * 4 + 2], o[r * 4 + 3]);
}

// ---------------------------------------------------------------------------
extern "C" void kernel_launch(void* const* d_in, const int* in_sizes, int n_in,
                              void* d_out, int out_size)
{
    const float* x      = (const float*)d_in[0];
    const float* mask   = (const float*)d_in[1];
    const float* qkv_w  = (const float*)d_in[2];
    const float* qkv_b  = (const float*)d_in[3];
    const float* proj_w = (const float*)d_in[4];
    const float* proj_b = (const float*)d_in[5];
    const float* table  = (const float*)d_in[6];
    const int*   relidx = (const int*)d_in[7];
    float* out = (float*)d_out;

    float* g_ao_ptr = nullptr;
    cudaGetSymbolAddress((void**)&g_ao_ptr, g_ao);

    cudaFuncSetAttribute(gemm_tf32<0>, cudaFuncAttributeMaxDynamicSharedMemorySize, GEMM_SMEM);
    cudaFuncSetAttribute(gemm_tf32<1>, cudaFuncAttributeMaxDynamicSharedMemorySize, GEMM_SMEM);

    // 0) pre-gather relative position bias per head
    bias_init_kernel<<<(HEADS * NTOK * NTOK + 255) / 256, 256>>>(table, relidx);

    // 1) QKV projection (tf32 mma.sync + cp.async pipeline)
    {
        dim3 grid(768 / 128, MROWS / 128);
        gemm_tf32<0><<<grid, 256, GEMM_SMEM>>>(x, qkv_w, qkv_b, nullptr, 768);
    }
    // 2) windowed attention
    attn_kernel<<<B_WIN * HEADS, 64>>>(mask);
    // 3) output projection
    {
        dim3 grid(256 / 128, MROWS / 128);
        gemm_tf32<1><<<grid, 256, GEMM_SMEM>>>(g_ao_ptr, proj_w, proj_b, out, CDIM);
    }
}

// round 14
// speedup vs baseline: 3.4505x; 1.2383x over previous
#include <cuda_runtime.h>
#include <cuda_fp16.h>
#include <cstdint>

// Problem constants
#define B_WIN   4096
#define NTOK    64
#define CDIM    256
#define HEADS   8
#define HDIM    32
#define NW      64
#define MROWS   (B_WIN * NTOK)          // 262144
#define QSCALE  0.17677669529663687f    // 32^-0.5

// Static scratch (allocation-free by rule)
__device__ float  g_q[(size_t)B_WIN * HEADS * NTOK * HDIM];
__device__ float  g_k[(size_t)B_WIN * HEADS * NTOK * HDIM];
__device__ float  g_v[(size_t)B_WIN * HEADS * NTOK * HDIM];
__device__ float  g_biasH[HEADS * NTOK * NTOK];       // [h][q][k] rel bias
__device__ __half g_xh[(size_t)MROWS * CDIM];         // fp16 x
__device__ __half g_wqkvh[768 * 256];                 // fp16 qkv_w
__device__ __half g_wprojh[256 * 256];                // fp16 proj_w
__device__ __half g_aoh[(size_t)MROWS * CDIM];        // fp16 attention output

__device__ __forceinline__ uint32_t smem_u32(const void* p) {
    uint32_t a;
    asm("{ .reg .u64 t; cvta.to.shared.u64 t, %1; cvt.u32.u64 %0, t; }" : "=r"(a) : "l"(p));
    return a;
}
__device__ __forceinline__ void cp_async16(uint32_t dst, const void* src) {
    asm volatile("cp.async.cg.shared.global [%0], [%1], 16;" :: "r"(dst), "l"(src) : "memory");
}
#define CP_COMMIT() asm volatile("cp.async.commit_group;" ::: "memory")
#define CP_WAIT(n)  asm volatile("cp.async.wait_group %0;" :: "n"(n) : "memory")

__device__ __forceinline__ void ldsm4(uint32_t& r0, uint32_t& r1, uint32_t& r2, uint32_t& r3,
                                      uint32_t addr) {
    asm volatile("ldmatrix.sync.aligned.m8n8.x4.shared.b16 {%0,%1,%2,%3}, [%4];"
                 : "=r"(r0), "=r"(r1), "=r"(r2), "=r"(r3) : "r"(addr));
}
__device__ __forceinline__ void mma_f16(float* c, const uint32_t* a, const uint32_t* b) {
    asm volatile(
        "mma.sync.aligned.m16n8k16.row.col.f32.f16.f16.f32 "
        "{%0,%1,%2,%3}, {%4,%5,%6,%7}, {%8,%9}, {%0,%1,%2,%3};"
        : "+f"(c[0]), "+f"(c[1]), "+f"(c[2]), "+f"(c[3])
        : "r"(a[0]), "r"(a[1]), "r"(a[2]), "r"(a[3]), "r"(b[0]), "r"(b[1]));
}

// ---------------------------------------------------------------------------
// fp32 -> fp16 conversion (8 elems/thread, vectorized)
// ---------------------------------------------------------------------------
__global__ void f2h_kernel(const float* __restrict__ src, __half* __restrict__ dst, int n8)
{
    int i = blockIdx.x * 256 + threadIdx.x;
    if (i >= n8) return;
    const float4* s = (const float4*)src + (size_t)i * 2;
    float4 v0 = s[0], v1 = s[1];
    __half2 hb[4];
    hb[0] = __floats2half2_rn(v0.x, v0.y);
    hb[1] = __floats2half2_rn(v0.z, v0.w);
    hb[2] = __floats2half2_rn(v1.x, v1.y);
    hb[3] = __floats2half2_rn(v1.z, v1.w);
    *(uint4*)(dst + (size_t)i * 8) = *(uint4*)hb;
}

// ---------------------------------------------------------------------------
// Init: biasH[h][q][k] = table[rel_index[q*64+k] * 8 + h]
// ---------------------------------------------------------------------------
__global__ void bias_init_kernel(const float* __restrict__ table,
                                 const int* __restrict__ rel_index)
{
    int idx = blockIdx.x * blockDim.x + threadIdx.x;
    if (idx >= HEADS * NTOK * NTOK) return;
    int h  = idx >> 12;
    int qk = idx & 4095;
    g_biasH[idx] = table[rel_index[qk] * HEADS + h];
}

// ---------------------------------------------------------------------------
// FP16 mma.sync GEMM, cp.async double-buffered, ldmatrix fragment loads.
// C[M,N] = A[M,256] @ B[N,256]^T (+bias). 128x128x32 tile, 256 thr, 8 warps.
// Smem rows: 32 halves padded to 40 (80B) -> conflict-free ldmatrix phases.
// MODE 0: QKV scatter epilogue (fp32 q/k/v); MODE 1: plain fp32 epilogue.
// ---------------------------------------------------------------------------
#define ROWB   80                       // bytes per smem row (32 halves + pad)
#define TILEB  (128 * ROWB)             // 10240 B per tile
#define STAGEB (2 * TILEB)              // A+B per stage

template <int MODE>
__global__ __launch_bounds__(256, 2)
void gemm_f16(const __half* __restrict__ A, const __half* __restrict__ B,
              const float* __restrict__ bias, float* __restrict__ C, int Ncols)
{
    __shared__ __align__(16) char sm[2][STAGEB];
    const uint32_t smb = smem_u32(sm);

    const int tid  = threadIdx.x;
    const int lane = tid & 31;
    const int gid  = lane >> 2;
    const int tig  = lane & 3;
    const int warpId = tid >> 5;
    const int wm = (warpId & 1) * 64;
    const int wn = (warpId >> 1) * 32;

    const size_t mBase = (size_t)blockIdx.y * 128;
    const size_t nBase = (size_t)blockIdx.x * 128;
    const __half* Ab = A + mBase * 256;
    const __half* Bb = B + nBase * 256;

    // ldmatrix lane-address offsets (bytes within tile)
    const uint32_t laneA = (uint32_t)(((((lane >> 3) & 1) * 8) + (lane & 7)) * ROWB
                                      + ((lane >> 4) & 1) * 16);
    const uint32_t laneB = (uint32_t)((lane & 7) * ROWB + ((lane >> 3) & 1) * 16
                                      + ((lane >> 4) & 1) * 8 * ROWB);

    auto load_stage = [&](int s, int buf) {
        const uint32_t bA = smb + (uint32_t)buf * STAGEB;
        const uint32_t bB = bA + TILEB;
#pragma unroll
        for (int p = 0; p < 2; p++) {
            int c  = tid + p * 256;     // 0..511
            int r  = c >> 2;            // row 0..127
            int cq = c & 3;             // 16B chunk (8 halves)
            uint32_t off = (uint32_t)r * ROWB + (uint32_t)cq * 16;
            cp_async16(bA + off, Ab + (size_t)r * 256 + s * 32 + cq * 8);
            cp_async16(bB + off, Bb + (size_t)r * 256 + s * 32 + cq * 8);
        }
        CP_COMMIT();
    };

    float acc[4][4][4];
#pragma unroll
    for (int i = 0; i < 4; i++)
#pragma unroll
        for (int j = 0; j < 4; j++)
#pragma unroll
            for (int r = 0; r < 4; r++) acc[i][j][r] = 0.f;

    load_stage(0, 0);

    for (int s = 0; s < 8; s++) {
        const int buf = s & 1;
        if (s < 7) { load_stage(s + 1, buf ^ 1); CP_WAIT(1); }
        else       { CP_WAIT(0); }
        __syncthreads();

        const uint32_t bA = smb + (uint32_t)buf * STAGEB + laneA;
        const uint32_t bB = smb + (uint32_t)buf * STAGEB + TILEB + laneB;

#pragma unroll
        for (int s2 = 0; s2 < 2; s2++) {
            uint32_t a[4][4], b[2][4];
#pragma unroll
            for (int i = 0; i < 4; i++)
                ldsm4(a[i][0], a[i][1], a[i][2], a[i][3],
                      bA + (uint32_t)(wm + 16 * i) * ROWB + s2 * 32);
            ldsm4(b[0][0], b[0][1], b[0][2], b[0][3],
                  bB + (uint32_t)wn * ROWB + s2 * 32);
            ldsm4(b[1][0], b[1][1], b[1][2], b[1][3],
                  bB + (uint32_t)(wn + 16) * ROWB + s2 * 32);
#pragma unroll
            for (int i = 0; i < 4; i++)
#pragma unroll
                for (int j = 0; j < 4; j++)
                    mma_f16(acc[i][j], a[i], &b[j >> 1][(j & 1) * 2]);
        }
        __syncthreads();
    }

    // ---- epilogue (same C-frag mapping as m16n8k8) ----
#pragma unroll
    for (int i = 0; i < 4; i++) {
#pragma unroll
        for (int j = 0; j < 4; j++) {
#pragma unroll
            for (int r = 0; r < 4; r++) {
                int m = (int)mBase + wm + 16 * i + gid + (r >> 1) * 8;
                int o = (int)nBase + wn + 8 * j + 2 * tig + (r & 1);
                float val = acc[i][j][r] + bias[o];
                if (MODE == 0) {
                    int b  = m >> 6;
                    int n  = m & 63;
                    int c3 = o >> 8;
                    int h  = (o >> 5) & 7;
                    int d  = o & 31;
                    size_t idx = ((((size_t)b * HEADS + h) * NTOK + n) * HDIM) + d;
                    if (c3 == 0)      g_q[idx] = val * QSCALE;
                    else if (c3 == 1) g_k[idx] = val;
                    else              g_v[idx] = val;
                } else {
                    C[(size_t)m * Ncols + o] = val;
                }
            }
        }
    }
}

// ---------------------------------------------------------------------------
// Attention: one block per (window, head), 64 threads = 1 query row each.
// Fully unrolled (register-resident scores). Output now stored as fp16.
// ---------------------------------------------------------------------------
__global__ __launch_bounds__(64)
void attn_kernel(const float* __restrict__ mask)
{
    const int bh = blockIdx.x;
    const int b  = bh >> 3;
    const int h  = bh & 7;
    const int t  = threadIdx.x;

    __shared__ float ks[NTOK * HDIM];
    __shared__ float vs[NTOK * HDIM];
    __shared__ float sadd[NTOK * 65];

    const float4* kb = (const float4*)(g_k + (size_t)bh * NTOK * HDIM);
    const float4* vb = (const float4*)(g_v + (size_t)bh * NTOK * HDIM);
#pragma unroll
    for (int r = 0; r < 8; r++) {
        int idx = r * 64 + t;
        ((float4*)ks)[idx] = kb[idx];
        ((float4*)vs)[idx] = vb[idx];
    }

    {
        const float* mrow = mask    + (size_t)(b & (NW - 1)) * (NTOK * NTOK);
        const float* brow = g_biasH + (size_t)h * (NTOK * NTOK);
#pragma unroll 8
        for (int i = 0; i < NTOK; i++)
            sadd[i * 65 + t] = mrow[i * 64 + t] + brow[i * 64 + t];
    }

    float q[32];
    {
        const float4* qrow = (const float4*)(g_q + (size_t)bh * NTOK * HDIM + (size_t)t * HDIM);
#pragma unroll
        for (int r = 0; r < 8; r++) {
            float4 v = qrow[r];
            q[r * 4 + 0] = v.x; q[r * 4 + 1] = v.y; q[r * 4 + 2] = v.z; q[r * 4 + 3] = v.w;
        }
    }
    __syncthreads();

    const float* my = sadd + t * 65;

    float sc[64];
    float mx = -1e30f;
#pragma unroll
    for (int j = 0; j < 64; j++) {
        const float4* kj = (const float4*)(ks + j * HDIM);
        float s = my[j];
#pragma unroll
        for (int r = 0; r < 8; r++) {
            float4 kv = kj[r];
            s = fmaf(q[r * 4 + 0], kv.x, s);
            s = fmaf(q[r * 4 + 1], kv.y, s);
            s = fmaf(q[r * 4 + 2], kv.z, s);
            s = fmaf(q[r * 4 + 3], kv.w, s);
        }
        sc[j] = s;
        mx = fmaxf(mx, s);
    }

    float sum = 0.f;
#pragma unroll
    for (int j = 0; j < 64; j++) {
        float e = __expf(sc[j] - mx);
        sc[j] = e;
        sum += e;
    }
    const float inv = 1.f / sum;

    float o[32];
#pragma unroll
    for (int d = 0; d < 32; d++) o[d] = 0.f;
#pragma unroll
    for (int j = 0; j < 64; j++) {
        float p = sc[j] * inv;
        const float4* vj = (const float4*)(vs + j * HDIM);
#pragma unroll
        for (int r = 0; r < 8; r++) {
            float4 vv = vj[r];
            o[r * 4 + 0] = fmaf(p, vv.x, o[r * 4 + 0]);
            o[r * 4 + 1] = fmaf(p, vv.y, o[r * 4 + 1]);
            o[r * 4 + 2] = fmaf(p, vv.z, o[r * 4 + 2]);
            o[r * 4 + 3] = fmaf(p, vv.w, o[r * 4 + 3]);
        }
    }

    // store as fp16 for the proj GEMM
    __half2 hb[16];
#pragma unroll
    for (int r = 0; r < 16; r++)
        hb[r] = __floats2half2_rn(o[r * 2], o[r * 2 + 1]);
    uint4* dst = (uint4*)(g_aoh + ((size_t)(b * NTOK + t) * CDIM) + h * HDIM);
#pragma unroll
    for (int r = 0; r < 4; r++)
        dst[r] = ((uint4*)hb)[r];
}

// ---------------------------------------------------------------------------
extern "C" void kernel_launch(void* const* d_in, const int* in_sizes, int n_in,
                              void* d_out, int out_size)
{
    const float* x      = (const float*)d_in[0];
    const float* mask   = (const float*)d_in[1];
    const float* qkv_w  = (const float*)d_in[2];
    const float* qkv_b  = (const float*)d_in[3];
    const float* proj_w = (const float*)d_in[4];
    const float* proj_b = (const float*)d_in[5];
    const float* table  = (const float*)d_in[6];
    const int*   relidx = (const int*)d_in[7];
    float* out = (float*)d_out;

    __half *xh_p, *wqkv_p, *wproj_p, *aoh_p;
    cudaGetSymbolAddress((void**)&xh_p,    g_xh);
    cudaGetSymbolAddress((void**)&wqkv_p,  g_wqkvh);
    cudaGetSymbolAddress((void**)&wproj_p, g_wprojh);
    cudaGetSymbolAddress((void**)&aoh_p,   g_aoh);

    // 0) conversions + bias pre-gather
    f2h_kernel<<<(MROWS * CDIM / 8 + 255) / 256, 256>>>(x, xh_p, MROWS * CDIM / 8);
    f2h_kernel<<<(768 * 256 / 8 + 255) / 256, 256>>>(qkv_w, wqkv_p, 768 * 256 / 8);
    f2h_kernel<<<(256 * 256 / 8 + 255) / 256, 256>>>(proj_w, wproj_p, 256 * 256 / 8);
    bias_init_kernel<<<(HEADS * NTOK * NTOK + 255) / 256, 256>>>(table, relidx);

    // 1) QKV projection (fp16 mma + ldmatrix + cp.async)
    {
        dim3 grid(768 / 128, MROWS / 128);
        gemm_f16<0><<<grid, 256>>>(xh_p, wqkv_p, qkv_b, nullptr, 768);
    }
    // 2) windowed attention
    attn_kernel<<<B_WIN * HEADS, 64>>>(mask);
    // 3) output projection
    {
        dim3 grid(256 / 128, MROWS / 128);
        gemm_f16<1><<<grid, 256>>>(aoh_p, wproj_p, proj_b, out, CDIM);
    }
}

// round 15
// speedup vs baseline: 6.7861x; 1.9667x over previous
#include <cuda_runtime.h>
#include <cuda_fp16.h>
#include <cstdint>

// Problem constants
#define B_WIN   4096
#define NTOK    64
#define CDIM    256
#define HEADS   8
#define HDIM    32
#define NW      64
#define MROWS   (B_WIN * NTOK)          // 262144
#define QSCALE  0.17677669529663687f    // 32^-0.5

// Static scratch (allocation-free by rule)
__device__ __half g_qh[(size_t)B_WIN * HEADS * NTOK * HDIM];  // fp16 q (scaled)
__device__ __half g_kh[(size_t)B_WIN * HEADS * NTOK * HDIM];
__device__ __half g_vh[(size_t)B_WIN * HEADS * NTOK * HDIM];
__device__ __half g_xh[(size_t)MROWS * CDIM];                 // fp16 x
__device__ __half g_wqkvh[768 * 256];
__device__ __half g_wprojh[256 * 256];
__device__ __half g_aoh[(size_t)MROWS * CDIM];                // fp16 attention out
__device__ float  g_addf[NW * HEADS * NTOK * NTOK];           // mask+bias combined (8MB)

__device__ __forceinline__ uint32_t smem_u32(const void* p) {
    uint32_t a;
    asm("{ .reg .u64 t; cvta.to.shared.u64 t, %1; cvt.u32.u64 %0, t; }" : "=r"(a) : "l"(p));
    return a;
}
__device__ __forceinline__ void cp_async16(uint32_t dst, const void* src) {
    asm volatile("cp.async.cg.shared.global [%0], [%1], 16;" :: "r"(dst), "l"(src) : "memory");
}
#define CP_COMMIT() asm volatile("cp.async.commit_group;" ::: "memory")
#define CP_WAIT(n)  asm volatile("cp.async.wait_group %0;" :: "n"(n) : "memory")

__device__ __forceinline__ void ldsm4(uint32_t& r0, uint32_t& r1, uint32_t& r2, uint32_t& r3,
                                      uint32_t addr) {
    asm volatile("ldmatrix.sync.aligned.m8n8.x4.shared.b16 {%0,%1,%2,%3}, [%4];"
                 : "=r"(r0), "=r"(r1), "=r"(r2), "=r"(r3) : "r"(addr));
}
__device__ __forceinline__ void ldsm4t(uint32_t& r0, uint32_t& r1, uint32_t& r2, uint32_t& r3,
                                       uint32_t addr) {
    asm volatile("ldmatrix.sync.aligned.m8n8.x4.trans.shared.b16 {%0,%1,%2,%3}, [%4];"
                 : "=r"(r0), "=r"(r1), "=r"(r2), "=r"(r3) : "r"(addr));
}
__device__ __forceinline__ void mma_f16(float* c, const uint32_t* a, const uint32_t* b) {
    asm volatile(
        "mma.sync.aligned.m16n8k16.row.col.f32.f16.f16.f32 "
        "{%0,%1,%2,%3}, {%4,%5,%6,%7}, {%8,%9}, {%0,%1,%2,%3};"
        : "+f"(c[0]), "+f"(c[1]), "+f"(c[2]), "+f"(c[3])
        : "r"(a[0]), "r"(a[1]), "r"(a[2]), "r"(a[3]), "r"(b[0]), "r"(b[1]));
}
__device__ __forceinline__ uint32_t packh2(float lo, float hi) {
    __half2 h = __floats2half2_rn(lo, hi);
    return *(uint32_t*)&h;
}

// ---------------------------------------------------------------------------
// fp32 -> fp16 conversion (8 elems/thread, vectorized)
// ---------------------------------------------------------------------------
__global__ void f2h_kernel(const float* __restrict__ src, __half* __restrict__ dst, int n8)
{
    int i = blockIdx.x * 256 + threadIdx.x;
    if (i >= n8) return;
    const float4* s = (const float4*)src + (size_t)i * 2;
    float4 v0 = s[0], v1 = s[1];
    __half2 hb[4];
    hb[0] = __floats2half2_rn(v0.x, v0.y);
    hb[1] = __floats2half2_rn(v0.z, v0.w);
    hb[2] = __floats2half2_rn(v1.x, v1.y);
    hb[3] = __floats2half2_rn(v1.z, v1.w);
    *(uint4*)(dst + (size_t)i * 8) = *(uint4*)hb;
}

// ---------------------------------------------------------------------------
// Init: g_addf[w][h][q][k] = mask[w][q][k] + table[rel_index[q][k]*8+h]
// ---------------------------------------------------------------------------
__global__ void addf_init_kernel(const float* __restrict__ mask,
                                 const float* __restrict__ table,
                                 const int* __restrict__ rel_index)
{
    int idx = blockIdx.x * 256 + threadIdx.x;
    if (idx >= NW * HEADS * NTOK * NTOK) return;
    int w  = idx >> 15;
    int h  = (idx >> 12) & 7;
    int qk = idx & 4095;
    g_addf[idx] = mask[w * 4096 + qk] + table[rel_index[qk] * HEADS + h];
}

// ---------------------------------------------------------------------------
// FP16 mma.sync GEMM, cp.async double-buffered, ldmatrix fragment loads.
// C[M,N] = A[M,256] @ B[N,256]^T (+bias). 128x128x32 tile, 256 thr, 8 warps.
// MODE 0: QKV epilogue -> fp16 q/k/v scatter; MODE 1: plain fp32 epilogue.
// ---------------------------------------------------------------------------
#define ROWB   80
#define TILEB  (128 * ROWB)
#define STAGEB (2 * TILEB)

template <int MODE>
__global__ __launch_bounds__(256, 2)
void gemm_f16(const __half* __restrict__ A, const __half* __restrict__ B,
              const float* __restrict__ bias, float* __restrict__ C, int Ncols)
{
    __shared__ __align__(16) char sm[2][STAGEB];
    const uint32_t smb = smem_u32(sm);

    const int tid  = threadIdx.x;
    const int lane = tid & 31;
    const int gid  = lane >> 2;
    const int tig  = lane & 3;
    const int warpId = tid >> 5;
    const int wm = (warpId & 1) * 64;
    const int wn = (warpId >> 1) * 32;

    const size_t mBase = (size_t)blockIdx.y * 128;
    const size_t nBase = (size_t)blockIdx.x * 128;
    const __half* Ab = A + mBase * 256;
    const __half* Bb = B + nBase * 256;

    const uint32_t laneA = (uint32_t)((lane & 15) * ROWB + (lane >> 4) * 16);
    const uint32_t laneB = (uint32_t)((lane & 7) * ROWB + ((lane >> 3) & 1) * 16
                                      + ((lane >> 4) & 1) * 8 * ROWB);

    auto load_stage = [&](int s, int buf) {
        const uint32_t bA = smb + (uint32_t)buf * STAGEB;
        const uint32_t bB = bA + TILEB;
#pragma unroll
        for (int p = 0; p < 2; p++) {
            int c  = tid + p * 256;
            int r  = c >> 2;
            int cq = c & 3;
            uint32_t off = (uint32_t)r * ROWB + (uint32_t)cq * 16;
            cp_async16(bA + off, Ab + (size_t)r * 256 + s * 32 + cq * 8);
            cp_async16(bB + off, Bb + (size_t)r * 256 + s * 32 + cq * 8);
        }
        CP_COMMIT();
    };

    float acc[4][4][4];
#pragma unroll
    for (int i = 0; i < 4; i++)
#pragma unroll
        for (int j = 0; j < 4; j++)
#pragma unroll
            for (int r = 0; r < 4; r++) acc[i][j][r] = 0.f;

    load_stage(0, 0);

    for (int s = 0; s < 8; s++) {
        const int buf = s & 1;
        if (s < 7) { load_stage(s + 1, buf ^ 1); CP_WAIT(1); }
        else       { CP_WAIT(0); }
        __syncthreads();

        const uint32_t bA = smb + (uint32_t)buf * STAGEB + laneA;
        const uint32_t bB = smb + (uint32_t)buf * STAGEB + TILEB + laneB;

#pragma unroll
        for (int s2 = 0; s2 < 2; s2++) {
            uint32_t a[4][4], b[2][4];
#pragma unroll
            for (int i = 0; i < 4; i++)
                ldsm4(a[i][0], a[i][1], a[i][2], a[i][3],
                      bA + (uint32_t)(wm + 16 * i) * ROWB + s2 * 32);
            ldsm4(b[0][0], b[0][1], b[0][2], b[0][3],
                  bB + (uint32_t)wn * ROWB + s2 * 32);
            ldsm4(b[1][0], b[1][1], b[1][2], b[1][3],
                  bB + (uint32_t)(wn + 16) * ROWB + s2 * 32);
#pragma unroll
            for (int i = 0; i < 4; i++)
#pragma unroll
                for (int j = 0; j < 4; j++)
                    mma_f16(acc[i][j], a[i], &b[j >> 1][(j & 1) * 2]);
        }
        __syncthreads();
    }

    // ---- epilogue ----
#pragma unroll
    for (int i = 0; i < 4; i++) {
#pragma unroll
        for (int j = 0; j < 4; j++) {
#pragma unroll
            for (int rp = 0; rp < 2; rp++) {
                int m = (int)mBase + wm + 16 * i + gid + rp * 8;
                int o = (int)nBase + wn + 8 * j + 2 * tig;
                float v0 = acc[i][j][rp * 2 + 0] + bias[o];
                float v1 = acc[i][j][rp * 2 + 1] + bias[o + 1];
                if (MODE == 0) {
                    int b  = m >> 6;
                    int n  = m & 63;
                    int c3 = o >> 8;
                    int h  = (o >> 5) & 7;
                    int d  = o & 31;
                    __half* dstb;
                    if (c3 == 0)      { dstb = g_qh; v0 *= QSCALE; v1 *= QSCALE; }
                    else if (c3 == 1) dstb = g_kh;
                    else              dstb = g_vh;
                    size_t idx = ((((size_t)b * HEADS + h) * NTOK + n) * HDIM) + d;
                    *(uint32_t*)(dstb + idx) = packh2(v0, v1);
                } else {
                    C[(size_t)m * Ncols + o]     = v0;
                    C[(size_t)m * Ncols + o + 1] = v1;
                }
            }
        }
    }
}

// ---------------------------------------------------------------------------
// MMA attention: one block per (window, head), 2 warps x 32 query rows.
// QK^T and PV on fp16 tensor cores, fragment softmax, fp16 output.
// ---------------------------------------------------------------------------
#define AROW 40   // halves per smem row (32 + 8 pad) = 80 B

__global__ __launch_bounds__(64)
void attn_mma_kernel()
{
    const int bh = blockIdx.x;
    const int b  = bh >> 3;
    const int h  = bh & 7;
    const int tid  = threadIdx.x;
    const int wid  = tid >> 5;
    const int lane = tid & 31;
    const int gid  = lane >> 2;
    const int tig  = lane & 3;

    __shared__ __align__(16) __half Qs[NTOK * AROW];
    __shared__ __align__(16) __half Ks[NTOK * AROW];
    __shared__ __align__(16) __half Vs[NTOK * AROW];

    // stage q/k/v fp16 tiles (each 64x32 = 4KB contiguous)
    {
        const uint4* qt = (const uint4*)(g_qh + (size_t)bh * NTOK * HDIM);
        const uint4* kt = (const uint4*)(g_kh + (size_t)bh * NTOK * HDIM);
        const uint4* vt = (const uint4*)(g_vh + (size_t)bh * NTOK * HDIM);
#pragma unroll
        for (int p = 0; p < 4; p++) {
            int idx = tid + p * 64;      // 0..255
            int row = idx >> 2;
            int ch  = idx & 3;
            int so  = row * AROW + ch * 8;
            *(uint4*)(Qs + so) = qt[idx];
            *(uint4*)(Ks + so) = kt[idx];
            *(uint4*)(Vs + so) = vt[idx];
        }
    }
    __syncthreads();

    const uint32_t smQ = smem_u32(Qs);
    const uint32_t smK = smem_u32(Ks);
    const uint32_t smV = smem_u32(Vs);
    const uint32_t laneA = (uint32_t)((lane & 15) * 80 + (lane >> 4) * 16);
    const uint32_t laneB = (uint32_t)((lane & 7) * 80 + ((lane >> 3) & 1) * 16
                                      + ((lane >> 4) & 1) * 8 * 80);
    const int mBase = wid * 32;

    // ---- scores: S = Q @ K^T  (M=32 rows of this warp, N=64, K=32) ----
    float sacc[2][8][4];
#pragma unroll
    for (int i = 0; i < 2; i++)
#pragma unroll
        for (int j = 0; j < 8; j++)
#pragma unroll
            for (int r = 0; r < 4; r++) sacc[i][j][r] = 0.f;

#pragma unroll
    for (int s2 = 0; s2 < 2; s2++) {
        uint32_t a[2][4], kb[4][4];
#pragma unroll
        for (int i = 0; i < 2; i++)
            ldsm4(a[i][0], a[i][1], a[i][2], a[i][3],
                  smQ + (uint32_t)(mBase + 16 * i) * 80 + laneA + s2 * 32);
#pragma unroll
        for (int n2 = 0; n2 < 4; n2++)
            ldsm4(kb[n2][0], kb[n2][1], kb[n2][2], kb[n2][3],
                  smK + (uint32_t)(16 * n2) * 80 + laneB + s2 * 32);
#pragma unroll
        for (int i = 0; i < 2; i++)
#pragma unroll
            for (int j = 0; j < 8; j++)
                mma_f16(sacc[i][j], a[i], &kb[j >> 1][(j & 1) * 2]);
    }

    // ---- add mask+bias (L2-resident combined table), softmax ----
    const float* tb = g_addf + (((size_t)(b & (NW - 1)) * HEADS + h) * NTOK) * NTOK;
#pragma unroll
    for (int i = 0; i < 2; i++) {
#pragma unroll
        for (int rp = 0; rp < 2; rp++) {
            const int row = mBase + 16 * i + gid + 8 * rp;
            const float2* tr = (const float2*)(tb + row * 64);
            float mx = -1e30f;
#pragma unroll
            for (int j = 0; j < 8; j++) {
                float2 ad = tr[4 * j + tig];
                float v0 = sacc[i][j][2 * rp]     + ad.x;
                float v1 = sacc[i][j][2 * rp + 1] + ad.y;
                sacc[i][j][2 * rp]     = v0;
                sacc[i][j][2 * rp + 1] = v1;
                mx = fmaxf(mx, fmaxf(v0, v1));
            }
            mx = fmaxf(mx, __shfl_xor_sync(0xffffffffu, mx, 1));
            mx = fmaxf(mx, __shfl_xor_sync(0xffffffffu, mx, 2));
            float sum = 0.f;
#pragma unroll
            for (int j = 0; j < 8; j++) {
                float e0 = __expf(sacc[i][j][2 * rp]     - mx);
                float e1 = __expf(sacc[i][j][2 * rp + 1] - mx);
                sacc[i][j][2 * rp]     = e0;
                sacc[i][j][2 * rp + 1] = e1;
                sum += e0 + e1;
            }
            sum += __shfl_xor_sync(0xffffffffu, sum, 1);
            sum += __shfl_xor_sync(0xffffffffu, sum, 2);
            const float inv = 1.f / sum;
#pragma unroll
            for (int j = 0; j < 8; j++) {
                sacc[i][j][2 * rp]     *= inv;
                sacc[i][j][2 * rp + 1] *= inv;
            }
        }
    }

    // ---- O = P @ V  (M=32, N=32, K=64); V[k][n] via ldmatrix.trans ----
    float oacc[2][4][4];
#pragma unroll
    for (int i = 0; i < 2; i++)
#pragma unroll
        for (int d2 = 0; d2 < 4; d2++)
#pragma unroll
            for (int r = 0; r < 4; r++) oacc[i][d2][r] = 0.f;

#pragma unroll
    for (int kk = 0; kk < 4; kk++) {
        uint32_t vb[2][4];
        ldsm4t(vb[0][0], vb[0][1], vb[0][2], vb[0][3],
               smV + (uint32_t)(16 * kk) * 80 + laneA);          // d 0..15
        ldsm4t(vb[1][0], vb[1][1], vb[1][2], vb[1][3],
               smV + (uint32_t)(16 * kk) * 80 + laneA + 32);     // d 16..31
#pragma unroll
        for (int i = 0; i < 2; i++) {
            uint32_t a[4];
            a[0] = packh2(sacc[i][2 * kk][0],     sacc[i][2 * kk][1]);
            a[1] = packh2(sacc[i][2 * kk][2],     sacc[i][2 * kk][3]);
            a[2] = packh2(sacc[i][2 * kk + 1][0], sacc[i][2 * kk + 1][1]);
            a[3] = packh2(sacc[i][2 * kk + 1][2], sacc[i][2 * kk + 1][3]);
#pragma unroll
            for (int d2 = 0; d2 < 4; d2++)
                mma_f16(oacc[i][d2], a, &vb[d2 >> 1][(d2 & 1) * 2]);
        }
    }

    // ---- store fp16 output [B, N, H, hd] ----
    __half* dst = g_aoh + (size_t)b * NTOK * CDIM + h * HDIM;
#pragma unroll
    for (int i = 0; i < 2; i++)
#pragma unroll
        for (int d2 = 0; d2 < 4; d2++)
#pragma unroll
            for (int rp = 0; rp < 2; rp++) {
                int row = mBase + 16 * i + gid + 8 * rp;
                int col = 8 * d2 + 2 * tig;
                *(uint32_t*)(dst + (size_t)row * CDIM + col) =
                    packh2(oacc[i][d2][2 * rp], oacc[i][d2][2 * rp + 1]);
            }
}

// ---------------------------------------------------------------------------
extern "C" void kernel_launch(void* const* d_in, const int* in_sizes, int n_in,
                              void* d_out, int out_size)
{
    const float* x      = (const float*)d_in[0];
    const float* mask   = (const float*)d_in[1];
    const float* qkv_w  = (const float*)d_in[2];
    const float* qkv_b  = (const float*)d_in[3];
    const float* proj_w = (const float*)d_in[4];
    const float* proj_b = (const float*)d_in[5];
    const float* table  = (const float*)d_in[6];
    const int*   relidx = (const int*)d_in[7];
    float* out = (float*)d_out;

    __half *xh_p, *wqkv_p, *wproj_p, *aoh_p;
    cudaGetSymbolAddress((void**)&xh_p,    g_xh);
    cudaGetSymbolAddress((void**)&wqkv_p,  g_wqkvh);
    cudaGetSymbolAddress((void**)&wproj_p, g_wprojh);
    cudaGetSymbolAddress((void**)&aoh_p,   g_aoh);

    // 0) conversions + combined mask/bias table
    f2h_kernel<<<(MROWS * CDIM / 8 + 255) / 256, 256>>>(x, xh_p, MROWS * CDIM / 8);
    f2h_kernel<<<(768 * 256 / 8 + 255) / 256, 256>>>(qkv_w, wqkv_p, 768 * 256 / 8);
    f2h_kernel<<<(256 * 256 / 8 + 255) / 256, 256>>>(proj_w, wproj_p, 256 * 256 / 8);
    addf_init_kernel<<<(NW * HEADS * NTOK * NTOK + 255) / 256, 256>>>(mask, table, relidx);

    // 1) QKV projection (fp16 mma + ldmatrix + cp.async) -> fp16 q/k/v
    {
        dim3 grid(768 / 128, MROWS / 128);
        gemm_f16<0><<<grid, 256>>>(xh_p, wqkv_p, qkv_b, nullptr, 768);
    }
    // 2) windowed attention on tensor cores
    attn_mma_kernel<<<B_WIN * HEADS, 64>>>();
    // 3) output projection
    {
        dim3 grid(256 / 128, MROWS / 128);
        gemm_f16<1><<<grid, 256>>>(aoh_p, wproj_p, proj_b, out, CDIM);
    }
}

// round 16
// speedup vs baseline: 7.1114x; 1.0479x over previous
#include <cuda_runtime.h>
#include <cuda_fp16.h>
#include <cstdint>

// Problem constants
#define B_WIN   4096
#define NTOK    64
#define CDIM    256
#define HEADS   8
#define HDIM    32
#define NW      64
#define MROWS   (B_WIN * NTOK)          // 262144
#define QSCALE  0.17677669529663687f    // 32^-0.5

// Static scratch (allocation-free by rule)
__device__ __half g_qh[(size_t)B_WIN * HEADS * NTOK * HDIM];  // fp16 q (scaled)
__device__ __half g_kh[(size_t)B_WIN * HEADS * NTOK * HDIM];
__device__ __half g_vh[(size_t)B_WIN * HEADS * NTOK * HDIM];
__device__ __half g_xh[(size_t)MROWS * CDIM];                 // fp16 x
__device__ __half g_wqkvh[768 * 256];
__device__ __half g_wprojh[256 * 256];
__device__ __half g_aoh[(size_t)MROWS * CDIM];                // fp16 attention out
__device__ float  g_addf[NW * HEADS * NTOK * NTOK];           // mask+bias combined (8MB)

__device__ __forceinline__ uint32_t smem_u32(const void* p) {
    uint32_t a;
    asm("{ .reg .u64 t; cvta.to.shared.u64 t, %1; cvt.u32.u64 %0, t; }" : "=r"(a) : "l"(p));
    return a;
}
__device__ __forceinline__ void cp_async16(uint32_t dst, const void* src) {
    asm volatile("cp.async.cg.shared.global [%0], [%1], 16;" :: "r"(dst), "l"(src) : "memory");
}
#define CP_COMMIT() asm volatile("cp.async.commit_group;" ::: "memory")
#define CP_WAIT(n)  asm volatile("cp.async.wait_group %0;" :: "n"(n) : "memory")

__device__ __forceinline__ void ldsm4(uint32_t& r0, uint32_t& r1, uint32_t& r2, uint32_t& r3,
                                      uint32_t addr) {
    asm volatile("ldmatrix.sync.aligned.m8n8.x4.shared.b16 {%0,%1,%2,%3}, [%4];"
                 : "=r"(r0), "=r"(r1), "=r"(r2), "=r"(r3) : "r"(addr));
}
__device__ __forceinline__ void ldsm4t(uint32_t& r0, uint32_t& r1, uint32_t& r2, uint32_t& r3,
                                       uint32_t addr) {
    asm volatile("ldmatrix.sync.aligned.m8n8.x4.trans.shared.b16 {%0,%1,%2,%3}, [%4];"
                 : "=r"(r0), "=r"(r1), "=r"(r2), "=r"(r3) : "r"(addr));
}
__device__ __forceinline__ void mma_f16(float* c, const uint32_t* a, const uint32_t* b) {
    asm volatile(
        "mma.sync.aligned.m16n8k16.row.col.f32.f16.f16.f32 "
        "{%0,%1,%2,%3}, {%4,%5,%6,%7}, {%8,%9}, {%0,%1,%2,%3};"
        : "+f"(c[0]), "+f"(c[1]), "+f"(c[2]), "+f"(c[3])
        : "r"(a[0]), "r"(a[1]), "r"(a[2]), "r"(a[3]), "r"(b[0]), "r"(b[1]));
}
__device__ __forceinline__ uint32_t packh2(float lo, float hi) {
    __half2 h = __floats2half2_rn(lo, hi);
    return *(uint32_t*)&h;
}

// ---------------------------------------------------------------------------
// fp32 -> fp16 conversion (8 elems/thread, vectorized)
// ---------------------------------------------------------------------------
__global__ void f2h_kernel(const float* __restrict__ src, __half* __restrict__ dst, int n8)
{
    int i = blockIdx.x * 256 + threadIdx.x;
    if (i >= n8) return;
    const float4* s = (const float4*)src + (size_t)i * 2;
    float4 v0 = s[0], v1 = s[1];
    __half2 hb[4];
    hb[0] = __floats2half2_rn(v0.x, v0.y);
    hb[1] = __floats2half2_rn(v0.z, v0.w);
    hb[2] = __floats2half2_rn(v1.x, v1.y);
    hb[3] = __floats2half2_rn(v1.z, v1.w);
    *(uint4*)(dst + (size_t)i * 8) = *(uint4*)hb;
}

// ---------------------------------------------------------------------------
// Init: g_addf[w][h][q][k] = mask[w][q][k] + table[rel_index[q][k]*8+h]
// ---------------------------------------------------------------------------
__global__ void addf_init_kernel(const float* __restrict__ mask,
                                 const float* __restrict__ table,
                                 const int* __restrict__ rel_index)
{
    int idx = blockIdx.x * 256 + threadIdx.x;
    if (idx >= NW * HEADS * NTOK * NTOK) return;
    int w  = idx >> 15;
    int h  = (idx >> 12) & 7;
    int qk = idx & 4095;
    g_addf[idx] = mask[w * 4096 + qk] + table[rel_index[qk] * HEADS + h];
}

// ---------------------------------------------------------------------------
// FP16 mma.sync GEMM, 3-stage cp.async pipeline, ldmatrix fragment loads.
// C[M,N] = A[M,256] @ B[N,256]^T (+bias). 128x128x32 tile, 256 thr, 8 warps.
// MODE 0: QKV epilogue -> smem-staged coalesced fp16 q/k/v block stores.
// MODE 1: plain fp32 epilogue.
// ---------------------------------------------------------------------------
#define ROWB   80
#define TILEB  (128 * ROWB)
#define STAGEB (2 * TILEB)              // 20480 B
#define NSTAGE 3
#define GSMEM  (NSTAGE * STAGEB)        // 61440 B

template <int MODE>
__global__ __launch_bounds__(256, 2)
void gemm_f16(const __half* __restrict__ A, const __half* __restrict__ B,
              const float* __restrict__ bias, float* __restrict__ C, int Ncols)
{
    extern __shared__ __align__(16) char dsm[];
    const uint32_t smb = smem_u32(dsm);

    const int tid  = threadIdx.x;
    const int lane = tid & 31;
    const int gid  = lane >> 2;
    const int tig  = lane & 3;
    const int warpId = tid >> 5;
    const int wm = (warpId & 1) * 64;
    const int wn = (warpId >> 1) * 32;

    const size_t mBase = (size_t)blockIdx.y * 128;
    const size_t nBase = (size_t)blockIdx.x * 128;
    const __half* Ab = A + mBase * 256;
    const __half* Bb = B + nBase * 256;

    const uint32_t laneA = (uint32_t)((lane & 15) * ROWB + (lane >> 4) * 16);
    const uint32_t laneB = (uint32_t)((lane & 7) * ROWB + ((lane >> 3) & 1) * 16
                                      + ((lane >> 4) & 1) * 8 * ROWB);

    auto load_stage = [&](int s, int buf) {
        const uint32_t bA = smb + (uint32_t)buf * STAGEB;
        const uint32_t bB = bA + TILEB;
#pragma unroll
        for (int p = 0; p < 2; p++) {
            int c  = tid + p * 256;
            int r  = c >> 2;
            int cq = c & 3;
            uint32_t off = (uint32_t)r * ROWB + (uint32_t)cq * 16;
            cp_async16(bA + off, Ab + (size_t)r * 256 + s * 32 + cq * 8);
            cp_async16(bB + off, Bb + (size_t)r * 256 + s * 32 + cq * 8);
        }
        CP_COMMIT();
    };

    float acc[4][4][4];
#pragma unroll
    for (int i = 0; i < 4; i++)
#pragma unroll
        for (int j = 0; j < 4; j++)
#pragma unroll
            for (int r = 0; r < 4; r++) acc[i][j][r] = 0.f;

    load_stage(0, 0);
    load_stage(1, 1);

    for (int s = 0; s < 8; s++) {
        const int buf = s % NSTAGE;
        if (s + 2 < 8) load_stage(s + 2, (s + 2) % NSTAGE);
        if (s < 6)      { CP_WAIT(2); }
        else if (s == 6){ CP_WAIT(1); }
        else            { CP_WAIT(0); }
        __syncthreads();

        const uint32_t bA = smb + (uint32_t)buf * STAGEB + laneA;
        const uint32_t bB = smb + (uint32_t)buf * STAGEB + TILEB + laneB;

#pragma unroll
        for (int s2 = 0; s2 < 2; s2++) {
            uint32_t a[4][4], b[2][4];
#pragma unroll
            for (int i = 0; i < 4; i++)
                ldsm4(a[i][0], a[i][1], a[i][2], a[i][3],
                      bA + (uint32_t)(wm + 16 * i) * ROWB + s2 * 32);
            ldsm4(b[0][0], b[0][1], b[0][2], b[0][3],
                  bB + (uint32_t)wn * ROWB + s2 * 32);
            ldsm4(b[1][0], b[1][1], b[1][2], b[1][3],
                  bB + (uint32_t)(wn + 16) * ROWB + s2 * 32);
#pragma unroll
            for (int i = 0; i < 4; i++)
#pragma unroll
                for (int j = 0; j < 4; j++)
                    mma_f16(acc[i][j], a[i], &b[j >> 1][(j & 1) * 2]);
        }
        __syncthreads();
    }

    if (MODE == 0) {
        // Each warp's 64x32 tile = one contiguous 4KB block of g_q/g_k/g_v:
        // o-range [nBase+wn, +32) fixes (c3, h); m-range is one 64-aligned window.
        const int o0 = (int)nBase + wn;
        const int c3 = o0 >> 8;
        const int h  = (o0 >> 5) & 7;
        const int b  = (int)(mBase + wm) >> 6;
        const float qs = (c3 == 0) ? QSCALE : 1.0f;
        __half* dstb = (c3 == 0) ? g_qh : ((c3 == 1) ? g_kh : g_vh);

        __half* ep = (__half*)dsm + warpId * 2048;   // 4KB per-warp staging
#pragma unroll
        for (int i = 0; i < 4; i++) {
#pragma unroll
            for (int j = 0; j < 4; j++) {
#pragma unroll
                for (int rp = 0; rp < 2; rp++) {
                    int row = 16 * i + gid + 8 * rp;
                    int col = 8 * j + 2 * tig;
                    float v0 = (acc[i][j][rp * 2 + 0] + bias[o0 + col])     * qs;
                    float v1 = (acc[i][j][rp * 2 + 1] + bias[o0 + col + 1]) * qs;
                    *(uint32_t*)(ep + row * 32 + col) = packh2(v0, v1);
                }
            }
        }
        __syncwarp();
        // coalesced 4KB blit: rows n=0..63 contiguous in [b][h] block
        uint4* dst = (uint4*)(dstb + (((size_t)b * HEADS + h) * NTOK) * HDIM);
        const uint4* src = (const uint4*)ep;
#pragma unroll
        for (int p = 0; p < 8; p++)
            dst[lane + p * 32] = src[lane + p * 32];
    } else {
#pragma unroll
        for (int i = 0; i < 4; i++) {
#pragma unroll
            for (int j = 0; j < 4; j++) {
#pragma unroll
                for (int rp = 0; rp < 2; rp++) {
                    int m = (int)mBase + wm + 16 * i + gid + rp * 8;
                    int o = (int)nBase + wn + 8 * j + 2 * tig;
                    float2 v;
                    v.x = acc[i][j][rp * 2 + 0] + bias[o];
                    v.y = acc[i][j][rp * 2 + 1] + bias[o + 1];
                    *(float2*)(C + (size_t)m * Ncols + o) = v;
                }
            }
        }
    }
}

// ---------------------------------------------------------------------------
// MMA attention: one block per (window, head), 2 warps x 32 query rows.
// ---------------------------------------------------------------------------
#define AROW 40   // halves per smem row (32 + 8 pad) = 80 B

__global__ __launch_bounds__(64)
void attn_mma_kernel()
{
    const int bh = blockIdx.x;
    const int b  = bh >> 3;
    const int h  = bh & 7;
    const int tid  = threadIdx.x;
    const int wid  = tid >> 5;
    const int lane = tid & 31;
    const int gid  = lane >> 2;
    const int tig  = lane & 3;

    __shared__ __align__(16) __half Qs[NTOK * AROW];
    __shared__ __align__(16) __half Ks[NTOK * AROW];
    __shared__ __align__(16) __half Vs[NTOK * AROW];

    {
        const uint4* qt = (const uint4*)(g_qh + (size_t)bh * NTOK * HDIM);
        const uint4* kt = (const uint4*)(g_kh + (size_t)bh * NTOK * HDIM);
        const uint4* vt = (const uint4*)(g_vh + (size_t)bh * NTOK * HDIM);
#pragma unroll
        for (int p = 0; p < 4; p++) {
            int idx = tid + p * 64;
            int row = idx >> 2;
            int ch  = idx & 3;
            int so  = row * AROW + ch * 8;
            *(uint4*)(Qs + so) = qt[idx];
            *(uint4*)(Ks + so) = kt[idx];
            *(uint4*)(Vs + so) = vt[idx];
        }
    }
    __syncthreads();

    const uint32_t smQ = smem_u32(Qs);
    const uint32_t smK = smem_u32(Ks);
    const uint32_t smV = smem_u32(Vs);
    const uint32_t laneA = (uint32_t)((lane & 15) * 80 + (lane >> 4) * 16);
    const uint32_t laneB = (uint32_t)((lane & 7) * 80 + ((lane >> 3) & 1) * 16
                                      + ((lane >> 4) & 1) * 8 * 80);
    const int mBase = wid * 32;

    float sacc[2][8][4];
#pragma unroll
    for (int i = 0; i < 2; i++)
#pragma unroll
        for (int j = 0; j < 8; j++)
#pragma unroll
            for (int r = 0; r < 4; r++) sacc[i][j][r] = 0.f;

#pragma unroll
    for (int s2 = 0; s2 < 2; s2++) {
        uint32_t a[2][4], kb[4][4];
#pragma unroll
        for (int i = 0; i < 2; i++)
            ldsm4(a[i][0], a[i][1], a[i][2], a[i][3],
                  smQ + (uint32_t)(mBase + 16 * i) * 80 + laneA + s2 * 32);
#pragma unroll
        for (int n2 = 0; n2 < 4; n2++)
            ldsm4(kb[n2][0], kb[n2][1], kb[n2][2], kb[n2][3],
                  smK + (uint32_t)(16 * n2) * 80 + laneB + s2 * 32);
#pragma unroll
        for (int i = 0; i < 2; i++)
#pragma unroll
            for (int j = 0; j < 8; j++)
                mma_f16(sacc[i][j], a[i], &kb[j >> 1][(j & 1) * 2]);
    }

    const float* tb = g_addf + (((size_t)(b & (NW - 1)) * HEADS + h) * NTOK) * NTOK;
#pragma unroll
    for (int i = 0; i < 2; i++) {
#pragma unroll
        for (int rp = 0; rp < 2; rp++) {
            const int row = mBase + 16 * i + gid + 8 * rp;
            const float2* tr = (const float2*)(tb + row * 64);
            float mx = -1e30f;
#pragma unroll
            for (int j = 0; j < 8; j++) {
                float2 ad = tr[4 * j + tig];
                float v0 = sacc[i][j][2 * rp]     + ad.x;
                float v1 = sacc[i][j][2 * rp + 1] + ad.y;
                sacc[i][j][2 * rp]     = v0;
                sacc[i][j][2 * rp + 1] = v1;
                mx = fmaxf(mx, fmaxf(v0, v1));
            }
            mx = fmaxf(mx, __shfl_xor_sync(0xffffffffu, mx, 1));
            mx = fmaxf(mx, __shfl_xor_sync(0xffffffffu, mx, 2));
            float sum = 0.f;
#pragma unroll
            for (int j = 0; j < 8; j++) {
                float e0 = __expf(sacc[i][j][2 * rp]     - mx);
                float e1 = __expf(sacc[i][j][2 * rp + 1] - mx);
                sacc[i][j][2 * rp]     = e0;
                sacc[i][j][2 * rp + 1] = e1;
                sum += e0 + e1;
            }
            sum += __shfl_xor_sync(0xffffffffu, sum, 1);
            sum += __shfl_xor_sync(0xffffffffu, sum, 2);
            const float inv = 1.f / sum;
#pragma unroll
            for (int j = 0; j < 8; j++) {
                sacc[i][j][2 * rp]     *= inv;
                sacc[i][j][2 * rp + 1] *= inv;
            }
        }
    }

    float oacc[2][4][4];
#pragma unroll
    for (int i = 0; i < 2; i++)
#pragma unroll
        for (int d2 = 0; d2 < 4; d2++)
#pragma unroll
            for (int r = 0; r < 4; r++) oacc[i][d2][r] = 0.f;

#pragma unroll
    for (int kk = 0; kk < 4; kk++) {
        uint32_t vb[2][4];
        ldsm4t(vb[0][0], vb[0][1], vb[0][2], vb[0][3],
               smV + (uint32_t)(16 * kk) * 80 + laneA);
        ldsm4t(vb[1][0], vb[1][1], vb[1][2], vb[1][3],
               smV + (uint32_t)(16 * kk) * 80 + laneA + 32);
#pragma unroll
        for (int i = 0; i < 2; i++) {
            uint32_t a[4];
            a[0] = packh2(sacc[i][2 * kk][0],     sacc[i][2 * kk][1]);
            a[1] = packh2(sacc[i][2 * kk][2],     sacc[i][2 * kk][3]);
            a[2] = packh2(sacc[i][2 * kk + 1][0], sacc[i][2 * kk + 1][1]);
            a[3] = packh2(sacc[i][2 * kk + 1][2], sacc[i][2 * kk + 1][3]);
#pragma unroll
            for (int d2 = 0; d2 < 4; d2++)
                mma_f16(oacc[i][d2], a, &vb[d2 >> 1][(d2 & 1) * 2]);
        }
    }

    __half* dst = g_aoh + (size_t)b * NTOK * CDIM + h * HDIM;
#pragma unroll
    for (int i = 0; i < 2; i++)
#pragma unroll
        for (int d2 = 0; d2 < 4; d2++)
#pragma unroll
            for (int rp = 0; rp < 2; rp++) {
                int row = mBase + 16 * i + gid + 8 * rp;
                int col = 8 * d2 + 2 * tig;
                *(uint32_t*)(dst + (size_t)row * CDIM + col) =
                    packh2(oacc[i][d2][2 * rp], oacc[i][d2][2 * rp + 1]);
            }
}

// ---------------------------------------------------------------------------
extern "C" void kernel_launch(void* const* d_in, const int* in_sizes, int n_in,
                              void* d_out, int out_size)
{
    const float* x      = (const float*)d_in[0];
    const float* mask   = (const float*)d_in[1];
    const float* qkv_w  = (const float*)d_in[2];
    const float* qkv_b  = (const float*)d_in[3];
    const float* proj_w = (const float*)d_in[4];
    const float* proj_b = (const float*)d_in[5];
    const float* table  = (const float*)d_in[6];
    const int*   relidx = (const int*)d_in[7];
    float* out = (float*)d_out;

    __half *xh_p, *wqkv_p, *wproj_p, *aoh_p;
    cudaGetSymbolAddress((void**)&xh_p,    g_xh);
    cudaGetSymbolAddress((void**)&wqkv_p,  g_wqkvh);
    cudaGetSymbolAddress((void**)&wproj_p, g_wprojh);
    cudaGetSymbolAddress((void**)&aoh_p,   g_aoh);

    cudaFuncSetAttribute(gemm_f16<0>, cudaFuncAttributeMaxDynamicSharedMemorySize, GSMEM);
    cudaFuncSetAttribute(gemm_f16<1>, cudaFuncAttributeMaxDynamicSharedMemorySize, GSMEM);

    // 0) conversions + combined mask/bias table
    f2h_kernel<<<(MROWS * CDIM / 8 + 255) / 256, 256>>>(x, xh_p, MROWS * CDIM / 8);
    f2h_kernel<<<(768 * 256 / 8 + 255) / 256, 256>>>(qkv_w, wqkv_p, 768 * 256 / 8);
    f2h_kernel<<<(256 * 256 / 8 + 255) / 256, 256>>>(proj_w, wproj_p, 256 * 256 / 8);
    addf_init_kernel<<<(NW * HEADS * NTOK * NTOK + 255) / 256, 256>>>(mask, table, relidx);

    // 1) QKV projection (fp16 mma + ldmatrix + 3-stage cp.async)
    {
        dim3 grid(768 / 128, MROWS / 128);
        gemm_f16<0><<<grid, 256, GSMEM>>>(xh_p, wqkv_p, qkv_b, nullptr, 768);
    }
    // 2) windowed attention on tensor cores
    attn_mma_kernel<<<B_WIN * HEADS, 64>>>();
    // 3) output projection
    {
        dim3 grid(256 / 128, MROWS / 128);
        gemm_f16<1><<<grid, 256, GSMEM>>>(aoh_p, wproj_p, proj_b, out, CDIM);
    }
}